// round 5
// baseline (speedup 1.0000x reference)
#include <cuda_runtime.h>
#include <cuda_bf16.h>
#include <math.h>
#include <stdint.h>

#define BB   2
#define SS   2048
#define DD   1024
#define HH   16
#define HD   64
#define DFF  4096
#define WIN  128
#define MTOT (BB * SS)

// ---------------- device scratch ----------------
__device__ float g_qkv [(size_t)MTOT * 3 * DD];
__device__ float g_attn[(size_t)MTOT * DD];
__device__ float g_tmp [(size_t)MTOT * DD];
__device__ float g_x2  [(size_t)MTOT * DD];
__device__ float g_ff  [(size_t)MTOT * DFF];

// int8 limbs (hi=*1, lo=*0) + per-row scales
__device__ int8_t g_xq1 [(size_t)MTOT*DD],   g_xq0 [(size_t)MTOT*DD];
__device__ int8_t g_atq1[(size_t)MTOT*DD],   g_atq0[(size_t)MTOT*DD];
__device__ int8_t g_x2q1[(size_t)MTOT*DD],   g_x2q0[(size_t)MTOT*DD];
__device__ int8_t g_ffq1[(size_t)MTOT*DFF],  g_ffq0[(size_t)MTOT*DFF];
__device__ int8_t g_iwq1[(size_t)3*DD*DD],   g_iwq0[(size_t)3*DD*DD];
__device__ int8_t g_owq1[(size_t)DD*DD],     g_owq0[(size_t)DD*DD];
__device__ int8_t g_w1q1[(size_t)DFF*DD],    g_w1q0[(size_t)DFF*DD];
__device__ int8_t g_w2q1[(size_t)DD*DFF],    g_w2q0[(size_t)DD*DFF];
__device__ float g_s_x[MTOT], g_s_at[MTOT], g_s_x2[MTOT], g_s_ff[MTOT];
__device__ float g_s_iw[3*DD], g_s_ow[DD], g_s_w1[DFF], g_s_w2[DD];

// ---------------- PTX helpers ----------------
__device__ __forceinline__ uint32_t smem_u32(const void* p) {
    uint32_t a;
    asm("{ .reg .u64 t; cvta.to.shared.u64 t, %1; cvt.u32.u64 %0, t; }" : "=r"(a) : "l"(p));
    return a;
}
__device__ __forceinline__ void cp16(uint32_t dst, const void* src) {
    asm volatile("cp.async.cg.shared.global [%0], [%1], 16;" :: "r"(dst), "l"(src));
}
__device__ __forceinline__ void cp_commit() {
    asm volatile("cp.async.commit_group;" ::: "memory");
}
template<int N>
__device__ __forceinline__ void cp_wait() {
    asm volatile("cp.async.wait_group %0;" :: "n"(N) : "memory");
}
__device__ __forceinline__ void imma(int32_t* c, const uint32_t* a, const uint32_t* b) {
    asm volatile(
        "mma.sync.aligned.m16n8k32.row.col.s32.s8.s8.s32 "
        "{%0,%1,%2,%3}, {%4,%5,%6,%7}, {%8,%9}, {%0,%1,%2,%3};"
        : "+r"(c[0]), "+r"(c[1]), "+r"(c[2]), "+r"(c[3])
        : "r"(a[0]), "r"(a[1]), "r"(a[2]), "r"(a[3]), "r"(b[0]), "r"(b[1]));
}
__device__ __forceinline__ void ldsm_x4(uint32_t* r, uint32_t addr) {
    asm volatile("ldmatrix.sync.aligned.m8n8.x4.shared.b16 {%0,%1,%2,%3}, [%4];"
                 : "=r"(r[0]), "=r"(r[1]), "=r"(r[2]), "=r"(r[3]) : "r"(addr));
}
__device__ __forceinline__ void ldsm_x2(uint32_t* r, uint32_t addr) {
    asm volatile("ldmatrix.sync.aligned.m8n8.x2.shared.b16 {%0,%1}, [%2];"
                 : "=r"(r[0]), "=r"(r[1]) : "r"(addr));
}

// ---------------- int8 2-limb GEMM ----------------
// C[M,N] = sA[m]*sB[n]*(16384*hh + 128*cross) + bias
// Block 128x128, BK=32, 256 thr, warps 2(m)x4(n), warp tile 64x32.
// Smem stage 16KB: A1|A0|B1|B0, each 128 rows x 32B, 16B units XOR-swizzled:
// unit (row, c) at (row>>3)*256 + ((row&7)*2 + (c ^ ((row&7)>>2)))*16.
#define STAGE_B 16384
#define GEMM_SMEM (3 * STAGE_B)

template<bool RELU>
__global__ __launch_bounds__(256, 1)
void gemm_s8(const int8_t* __restrict__ A1p, const int8_t* __restrict__ A0p,
             const int8_t* __restrict__ B1p, const int8_t* __restrict__ B0p,
             const float* __restrict__ sA, const float* __restrict__ sB,
             const float* __restrict__ bias, float* __restrict__ C,
             int M, int N, int K)
{
    extern __shared__ __align__(1024) int8_t smq[];
    const uint32_t sbase = smem_u32(smq);
    const int tid = threadIdx.x;
    const int warp = tid >> 5, lane = tid & 31;
    const int gid = lane >> 2, tig = lane & 3;
    const int wm = warp >> 2, wn = warp & 3;
    const int bx = blockIdx.x, by = blockIdx.y;

    const int8_t* matp[4] = {
        A1p + (size_t)(by * 128) * K, A0p + (size_t)(by * 128) * K,
        B1p + (size_t)(bx * 128) * K, B0p + (size_t)(bx * 128) * K };

    // loader: 1024 units of 16B per stage, 4 per thread
    int  l_mat[4], l_row[4], l_c[4];
    uint32_t l_dst[4];
#pragma unroll
    for (int i = 0; i < 4; i++) {
        int u = i * 256 + tid;
        l_mat[i] = u >> 8;
        l_row[i] = (u & 255) >> 1;
        l_c[i]   = u & 1;
        int r7 = l_row[i] & 7;
        l_dst[i] = (uint32_t)(l_mat[i] * 4096 + (l_row[i] >> 3) * 256 +
                              (r7 * 2 + (l_c[i] ^ (r7 >> 2))) * 16);
    }
    auto load_stage = [&](int chunk, int s) {
        const int k0 = chunk * 32;
        const uint32_t sb = sbase + s * STAGE_B;
#pragma unroll
        for (int i = 0; i < 4; i++)
            cp16(sb + l_dst[i], matp[l_mat[i]] + (size_t)l_row[i] * K + k0 + l_c[i] * 16);
        cp_commit();
    };

    // ldmatrix per-lane addresses
    const int l7 = lane & 7;
    const uint32_t a_off = (uint32_t)(((lane >> 3) & 1) * 256 +
        (l7 * 2 + ((lane >> 4) ^ (l7 >> 2))) * 16 + wm * 8 * 256);
    const int lm7 = lane & 7;
    const uint32_t b_off = (uint32_t)(
        (lm7 * 2 + (((lane >> 3) & 1) ^ (lm7 >> 2))) * 16 + wn * 4 * 256);

    int32_t hh[4][4][4], cr[4][4][4];
#pragma unroll
    for (int i = 0; i < 4; i++)
#pragma unroll
        for (int j = 0; j < 4; j++)
#pragma unroll
            for (int v = 0; v < 4; v++) { hh[i][j][v] = 0; cr[i][j][v] = 0; }

    const int nch = K >> 5;
    load_stage(0, 0);
    load_stage(1, 1);

    for (int c = 0; c < nch; c++) {
        cp_wait<1>();
        __syncthreads();
        if (c + 2 < nch) load_stage(c + 2, (c + 2) % 3);

        const uint32_t st = sbase + (c % 3) * STAGE_B;
        uint32_t b1f[4][2], b0f[4][2];
#pragma unroll
        for (int nt = 0; nt < 4; nt++) {
            const uint32_t ba = st + 8192 + b_off + nt * 256;
            ldsm_x2(b1f[nt], ba);
            ldsm_x2(b0f[nt], ba + 4096);
        }
#pragma unroll
        for (int mt = 0; mt < 4; mt++) {
            const uint32_t aa = st + a_off + mt * 512;
            uint32_t a1f[4], a0f[4];
            ldsm_x4(a1f, aa);
            ldsm_x4(a0f, aa + 4096);
#pragma unroll
            for (int nt = 0; nt < 4; nt++) {
                imma(hh[mt][nt], a1f, b1f[nt]);
                imma(cr[mt][nt], a1f, b0f[nt]);
                imma(cr[mt][nt], a0f, b1f[nt]);
            }
        }
    }

    // epilogue
#pragma unroll
    for (int mt = 0; mt < 4; mt++) {
#pragma unroll
        for (int nt = 0; nt < 4; nt++) {
            const int col = bx * 128 + wn * 32 + nt * 8 + tig * 2;
            const float sb0 = sB[col], sb1 = sB[col + 1];
            const float2 bb = *(const float2*)&bias[col];
            const int row0 = by * 128 + wm * 64 + mt * 16 + gid;
#pragma unroll
            for (int half = 0; half < 2; half++) {
                const int row = row0 + half * 8;
                const float sa = sA[row];
                float v0 = fmaf(16384.f, (float)hh[mt][nt][half*2],
                                128.f * (float)cr[mt][nt][half*2]) * sa * sb0 + bb.x;
                float v1 = fmaf(16384.f, (float)hh[mt][nt][half*2+1],
                                128.f * (float)cr[mt][nt][half*2+1]) * sa * sb1 + bb.y;
                if (RELU) { v0 = fmaxf(v0, 0.f); v1 = fmaxf(v1, 0.f); }
                *(float2*)(C + (size_t)row * N + col) = make_float2(v0, v1);
            }
        }
    }
}

// ---------------- per-row quantize: fp32 -> 2x int8 limbs + scale ----------------
__global__ __launch_bounds__(256)
void quant_rows(const float* __restrict__ src, int8_t* __restrict__ q1,
                int8_t* __restrict__ q0, float* __restrict__ scale, int K)
{
    const int row = blockIdx.x;
    const int t = threadIdx.x;
    const float4* s4 = (const float4*)(src + (size_t)row * K);
    const int n4 = K >> 2;

    float amax = 0.f;
    for (int i = t; i < n4; i += 256) {
        float4 v = s4[i];
        amax = fmaxf(amax, fmaxf(fmaxf(fabsf(v.x), fabsf(v.y)),
                                 fmaxf(fabsf(v.z), fabsf(v.w))));
    }
#pragma unroll
    for (int off = 16; off > 0; off >>= 1)
        amax = fmaxf(amax, __shfl_xor_sync(0xFFFFFFFFu, amax, off));
    __shared__ float wmax[8];
    __shared__ float s_inv;
    if ((t & 31) == 0) wmax[t >> 5] = amax;
    __syncthreads();
    if (t == 0) {
        float m = 0.f;
#pragma unroll
        for (int i = 0; i < 8; i++) m = fmaxf(m, wmax[i]);
        m = fmaxf(m, 1e-20f);
        s_inv = 16256.f / m;
        scale[row] = m / 16256.f;
    }
    __syncthreads();
    const float inv = s_inv;

    char4* o1 = (char4*)(q1 + (size_t)row * K);
    char4* o0 = (char4*)(q0 + (size_t)row * K);
    for (int i = t; i < n4; i += 256) {
        float4 v = s4[i];
        int aq[4] = { __float2int_rn(v.x * inv), __float2int_rn(v.y * inv),
                      __float2int_rn(v.z * inv), __float2int_rn(v.w * inv) };
        char4 c1, c0;
        int a1;
        a1 = (aq[0] + (aq[0] >= 0 ? 64 : -64)) / 128; c1.x = (char)a1; c0.x = (char)(aq[0] - (a1 << 7));
        a1 = (aq[1] + (aq[1] >= 0 ? 64 : -64)) / 128; c1.y = (char)a1; c0.y = (char)(aq[1] - (a1 << 7));
        a1 = (aq[2] + (aq[2] >= 0 ? 64 : -64)) / 128; c1.z = (char)a1; c0.z = (char)(aq[2] - (a1 << 7));
        a1 = (aq[3] + (aq[3] >= 0 ? 64 : -64)) / 128; c1.w = (char)a1; c0.w = (char)(aq[3] - (a1 << 7));
        o1[i] = c1;
        o0[i] = c0;
    }
}

// ---------------- banded flash attention (fp32) ----------------
__global__ __launch_bounds__(1024)
void attn_kernel(const float* __restrict__ qkv, float* __restrict__ attn_out)
{
    const int b  = blockIdx.z;
    const int h  = blockIdx.y;
    const int q0 = blockIdx.x * 32;
    const int warp = threadIdx.x >> 5;
    const int lane = threadIdx.x & 31;
    const int q = q0 + warp;

    const float* base = qkv + (size_t)b * SS * (3 * DD);
    const int hc = h * HD;

    const float q0r = base[(size_t)q * (3 * DD) + hc + lane];
    const float q1r = base[(size_t)q * (3 * DD) + hc + lane + 32];

    const int klo = max(q0 - WIN, 0);
    const int khi = min(q0 + 31 + WIN, SS - 1);

    __shared__ float Ks[32][64];
    __shared__ float Vs[32][64];

    float m = -1e30f, lsum = 0.f, acc0 = 0.f, acc1 = 0.f;

    for (int c = klo; c <= khi; c += 32) {
        const int nk = min(32, khi - c + 1);
        __syncthreads();
        for (int idx = threadIdx.x; idx < nk * 64; idx += 1024) {
            int j = idx >> 6, d = idx & 63;
            size_t row = (size_t)(c + j) * (3 * DD);
            Ks[j][d] = base[row + DD + hc + d];
            Vs[j][d] = base[row + 2 * DD + hc + d];
        }
        __syncthreads();

        const int jlo = max(q - WIN, c) - c;
        const int jhi = min(q + WIN, c + nk - 1) - c;
        for (int j = jlo; j <= jhi; j++) {
            float partial = q0r * Ks[j][lane] + q1r * Ks[j][lane + 32];
#pragma unroll
            for (int off = 16; off > 0; off >>= 1)
                partial += __shfl_xor_sync(0xFFFFFFFFu, partial, off);
            float s = partial * 0.125f;
            float nm = fmaxf(m, s);
            float scale = __expf(m - nm);
            float p = __expf(s - nm);
            lsum = lsum * scale + p;
            acc0 = acc0 * scale + p * Vs[j][lane];
            acc1 = acc1 * scale + p * Vs[j][lane + 32];
            m = nm;
        }
    }

    const float inv = 1.f / lsum;
    float* orow = attn_out + ((size_t)b * SS + q) * DD + hc;
    orow[lane]      = acc0 * inv;
    orow[lane + 32] = acc1 * inv;
}

// ---------------- fused residual + LayerNorm ----------------
__global__ __launch_bounds__(256)
void ln_kernel(const float* __restrict__ A, const float* __restrict__ R,
               const float* __restrict__ g, const float* __restrict__ be,
               float* __restrict__ out)
{
    const int row = blockIdx.x;
    const int t = threadIdx.x;
    const size_t base = (size_t)row * DD;

    float4 av = *(const float4*)(A + base + t * 4);
    float4 rv = *(const float4*)(R + base + t * 4);
    float4 v = make_float4(av.x + rv.x, av.y + rv.y, av.z + rv.z, av.w + rv.w);

    float s = v.x + v.y + v.z + v.w;
    float q = v.x * v.x + v.y * v.y + v.z * v.z + v.w * v.w;
#pragma unroll
    for (int off = 16; off > 0; off >>= 1) {
        s += __shfl_xor_sync(0xFFFFFFFFu, s, off);
        q += __shfl_xor_sync(0xFFFFFFFFu, q, off);
    }
    __shared__ float ss[8], sq[8];
    __shared__ float mu_s, inv_s;
    if ((t & 31) == 0) { ss[t >> 5] = s; sq[t >> 5] = q; }
    __syncthreads();
    if (t == 0) {
        float S = 0.f, Q = 0.f;
#pragma unroll
        for (int i = 0; i < 8; i++) { S += ss[i]; Q += sq[i]; }
        float mu = S * (1.f / DD);
        float var = Q * (1.f / DD) - mu * mu;
        mu_s = mu;
        inv_s = rsqrtf(var + 1e-5f);
    }
    __syncthreads();
    const float mu = mu_s, inv = inv_s;

    float4 gv = *(const float4*)(g + t * 4);
    float4 bv = *(const float4*)(be + t * 4);
    float4 o;
    o.x = (v.x - mu) * inv * gv.x + bv.x;
    o.y = (v.y - mu) * inv * gv.y + bv.y;
    o.z = (v.z - mu) * inv * gv.z + bv.z;
    o.w = (v.w - mu) * inv * gv.w + bv.w;
    *(float4*)(out + base + t * 4) = o;
}

// ---------------- host ----------------
extern "C" void kernel_launch(void* const* d_in, const int* in_sizes, int n_in,
                              void* d_out, int out_size)
{
    (void)in_sizes; (void)n_in; (void)out_size;
    const float* x     = (const float*)d_in[0];
    const float* in_w  = (const float*)d_in[1];
    const float* in_b  = (const float*)d_in[2];
    const float* out_w = (const float*)d_in[3];
    const float* out_b = (const float*)d_in[4];
    const float* ln1g  = (const float*)d_in[5];
    const float* ln1b  = (const float*)d_in[6];
    const float* w1    = (const float*)d_in[7];
    const float* b1    = (const float*)d_in[8];
    const float* w2    = (const float*)d_in[9];
    const float* b2    = (const float*)d_in[10];
    const float* ln2g  = (const float*)d_in[11];
    const float* ln2b  = (const float*)d_in[12];
    float* out = (float*)d_out;

    float *qkv, *attn, *tmp, *x2, *ff;
    int8_t *xq1, *xq0, *atq1, *atq0, *x2q1, *x2q0, *ffq1, *ffq0;
    int8_t *iwq1, *iwq0, *owq1, *owq0, *w1q1, *w1q0, *w2q1, *w2q0;
    float *s_x, *s_at, *s_x2, *s_ff, *s_iw, *s_ow, *s_w1, *s_w2;
    cudaGetSymbolAddress((void**)&qkv,  g_qkv);
    cudaGetSymbolAddress((void**)&attn, g_attn);
    cudaGetSymbolAddress((void**)&tmp,  g_tmp);
    cudaGetSymbolAddress((void**)&x2,   g_x2);
    cudaGetSymbolAddress((void**)&ff,   g_ff);
    cudaGetSymbolAddress((void**)&xq1,  g_xq1);  cudaGetSymbolAddress((void**)&xq0,  g_xq0);
    cudaGetSymbolAddress((void**)&atq1, g_atq1); cudaGetSymbolAddress((void**)&atq0, g_atq0);
    cudaGetSymbolAddress((void**)&x2q1, g_x2q1); cudaGetSymbolAddress((void**)&x2q0, g_x2q0);
    cudaGetSymbolAddress((void**)&ffq1, g_ffq1); cudaGetSymbolAddress((void**)&ffq0, g_ffq0);
    cudaGetSymbolAddress((void**)&iwq1, g_iwq1); cudaGetSymbolAddress((void**)&iwq0, g_iwq0);
    cudaGetSymbolAddress((void**)&owq1, g_owq1); cudaGetSymbolAddress((void**)&owq0, g_owq0);
    cudaGetSymbolAddress((void**)&w1q1, g_w1q1); cudaGetSymbolAddress((void**)&w1q0, g_w1q0);
    cudaGetSymbolAddress((void**)&w2q1, g_w2q1); cudaGetSymbolAddress((void**)&w2q0, g_w2q0);
    cudaGetSymbolAddress((void**)&s_x,  g_s_x);  cudaGetSymbolAddress((void**)&s_at, g_s_at);
    cudaGetSymbolAddress((void**)&s_x2, g_s_x2); cudaGetSymbolAddress((void**)&s_ff, g_s_ff);
    cudaGetSymbolAddress((void**)&s_iw, g_s_iw); cudaGetSymbolAddress((void**)&s_ow, g_s_ow);
    cudaGetSymbolAddress((void**)&s_w1, g_s_w1); cudaGetSymbolAddress((void**)&s_w2, g_s_w2);

    cudaFuncSetAttribute(gemm_s8<false>, cudaFuncAttributeMaxDynamicSharedMemorySize, GEMM_SMEM);
    cudaFuncSetAttribute(gemm_s8<true>,  cudaFuncAttributeMaxDynamicSharedMemorySize, GEMM_SMEM);

    // quantize weights + input
    quant_rows<<<3 * DD, 256>>>(in_w,  iwq1, iwq0, s_iw, DD);
    quant_rows<<<DD,     256>>>(out_w, owq1, owq0, s_ow, DD);
    quant_rows<<<DFF,    256>>>(w1,    w1q1, w1q0, s_w1, DD);
    quant_rows<<<DD,     256>>>(w2,    w2q1, w2q0, s_w2, DFF);
    quant_rows<<<MTOT,   256>>>(x,     xq1,  xq0,  s_x,  DD);

    // 1. QKV projection
    gemm_s8<false><<<dim3(3 * DD / 128, MTOT / 128), 256, GEMM_SMEM>>>(
        xq1, xq0, iwq1, iwq0, s_x, s_iw, in_b, qkv, MTOT, 3 * DD, DD);
    // 2. attention
    attn_kernel<<<dim3(SS / 32, HH, BB), 1024>>>(qkv, attn);
    // 3. out_proj
    quant_rows<<<MTOT, 256>>>(attn, atq1, atq0, s_at, DD);
    gemm_s8<false><<<dim3(DD / 128, MTOT / 128), 256, GEMM_SMEM>>>(
        atq1, atq0, owq1, owq0, s_at, s_ow, out_b, tmp, MTOT, DD, DD);
    // 4. ln1
    ln_kernel<<<MTOT, 256>>>(x, tmp, ln1g, ln1b, x2);
    // 5. ffn1 (relu)
    quant_rows<<<MTOT, 256>>>(x2, x2q1, x2q0, s_x2, DD);
    gemm_s8<true><<<dim3(DFF / 128, MTOT / 128), 256, GEMM_SMEM>>>(
        x2q1, x2q0, w1q1, w1q0, s_x2, s_w1, b1, ff, MTOT, DFF, DD);
    // 6. ffn2
    quant_rows<<<MTOT, 256>>>(ff, ffq1, ffq0, s_ff, DFF);
    gemm_s8<false><<<dim3(DD / 128, MTOT / 128), 256, GEMM_SMEM>>>(
        ffq1, ffq0, w2q1, w2q0, s_ff, s_w2, b2, tmp, MTOT, DD, DFF);
    // 7. ln2 -> final out
    ln_kernel<<<MTOT, 256>>>(x2, tmp, ln2g, ln2b, out);
}

// round 6
// speedup vs baseline: 2.6558x; 2.6558x over previous
#include <cuda_runtime.h>
#include <cuda_fp16.h>
#include <math.h>
#include <stdint.h>

#define BB   2
#define SS   2048
#define DD   1024
#define HH   16
#define HD   64
#define DFF  4096
#define WIN  128
#define MTOT (BB * SS)

// ---------------- device scratch ----------------
__device__ float  g_qkv [(size_t)MTOT * 3 * DD];
__device__ float  g_tmp [(size_t)MTOT * DD];
__device__ float  g_x2  [(size_t)MTOT * DD];
__device__ __half g_x_h [(size_t)MTOT * DD];
__device__ __half g_at_h[(size_t)MTOT * DD];
__device__ __half g_x2_h[(size_t)MTOT * DD];
__device__ __half g_ff_h[(size_t)MTOT * DFF];
__device__ __half g_iw_h[(size_t)3*DD*DD];
__device__ __half g_ow_h[(size_t)DD*DD];
__device__ __half g_w1_h[(size_t)DFF*DD];
__device__ __half g_w2_h[(size_t)DD*DFF];

// ---------------- PTX helpers ----------------
__device__ __forceinline__ uint32_t smem_u32(const void* p) {
    uint32_t a;
    asm("{ .reg .u64 t; cvta.to.shared.u64 t, %1; cvt.u32.u64 %0, t; }" : "=r"(a) : "l"(p));
    return a;
}
__device__ __forceinline__ void cp16(uint32_t dst, const void* src) {
    asm volatile("cp.async.cg.shared.global [%0], [%1], 16;" :: "r"(dst), "l"(src));
}
__device__ __forceinline__ void cp_commit() {
    asm volatile("cp.async.commit_group;" ::: "memory");
}
template<int N>
__device__ __forceinline__ void cp_wait() {
    asm volatile("cp.async.wait_group %0;" :: "n"(N) : "memory");
}
__device__ __forceinline__ void mma_f16(float* c, const uint32_t* a, const uint32_t* b) {
    asm volatile(
        "mma.sync.aligned.m16n8k16.row.col.f32.f16.f16.f32 "
        "{%0,%1,%2,%3}, {%4,%5,%6,%7}, {%8,%9}, {%0,%1,%2,%3};"
        : "+f"(c[0]), "+f"(c[1]), "+f"(c[2]), "+f"(c[3])
        : "r"(a[0]), "r"(a[1]), "r"(a[2]), "r"(a[3]), "r"(b[0]), "r"(b[1]));
}
__device__ __forceinline__ void ldsm_x4(uint32_t* r, uint32_t addr) {
    asm volatile("ldmatrix.sync.aligned.m8n8.x4.shared.b16 {%0,%1,%2,%3}, [%4];"
                 : "=r"(r[0]), "=r"(r[1]), "=r"(r[2]), "=r"(r[3]) : "r"(addr));
}
__device__ __forceinline__ void ldsm_x2(uint32_t* r, uint32_t addr) {
    asm volatile("ldmatrix.sync.aligned.m8n8.x2.shared.b16 {%0,%1}, [%2];"
                 : "=r"(r[0]), "=r"(r[1]) : "r"(addr));
}

// ---------------- fp16 GEMM via mma.sync ----------------
// C[M,N] = A[M,K] @ B[N,K]^T + bias.  A,B fp16, accum fp32.
// Block 256(M) x 128(N), BK=32, 512 thr, warp grid 4(m)x4(n), warp tile 64x32.
// Smem rows padded to 40 halves (80B): conflict-free ldmatrix + cp.async.
#define PITCH   40
#define A_MAT   (256 * PITCH)              // 10240 elems
#define B_MAT   (128 * PITCH)              // 5120 elems
#define STAGE_E (A_MAT + B_MAT)            // 15360 elems
#define GEMM_SMEM (2 * STAGE_E * 2)        // 61440 bytes

template<bool RELU, bool WF32, bool WF16>
__global__ __launch_bounds__(512, 1)
void gemm_f16(const __half* __restrict__ A, const __half* __restrict__ B,
              const float* __restrict__ bias,
              float* __restrict__ C, __half* __restrict__ Ch,
              int M, int N, int K)
{
    extern __shared__ __align__(16) __half sm[];
    const uint32_t sbase = smem_u32(sm);
    const int tid  = threadIdx.x;
    const int warp = tid >> 5, lane = tid & 31;
    const int gid  = lane >> 2, tig = lane & 3;
    const int wm   = warp >> 2;          // 0..3
    const int wn   = warp & 3;           // 0..3
    const int bx = blockIdx.x, by = blockIdx.y;

    const size_t Abase = (size_t)(by * 256) * K;
    const size_t Bbase = (size_t)(bx * 128) * K;

    // stage loader: 1536 16B chunks (A:1024, B:512), 3 per thread
    auto load_stage = [&](int chunk, int s) {
        const int k0 = chunk * 32;
        const uint32_t sb = sbase + s * (STAGE_E * 2);
#pragma unroll
        for (int i = 0; i < 3; i++) {
            int idx = i * 512 + tid;
            if (idx < 1024) {                       // A
                int r = idx >> 2, c16 = idx & 3;
                uint32_t dst = sb + (uint32_t)(r * PITCH + c16 * 8) * 2;
                cp16(dst, A + Abase + (size_t)r * K + k0 + c16 * 8);
            } else {                                // B
                int j = idx - 1024;
                int r = j >> 2, c16 = j & 3;
                uint32_t dst = sb + (uint32_t)(A_MAT + r * PITCH + c16 * 8) * 2;
                cp16(dst, B + Bbase + (size_t)r * K + k0 + c16 * 8);
            }
        }
        cp_commit();
    };

    float acc[4][4][4];
#pragma unroll
    for (int i = 0; i < 4; i++)
#pragma unroll
        for (int j = 0; j < 4; j++)
#pragma unroll
            for (int v = 0; v < 4; v++) acc[i][j][v] = 0.f;

    // per-lane ldmatrix offsets (bytes)
    const uint32_t a_off = (uint32_t)((wm * 64 + (lane & 15)) * PITCH + (lane >> 4) * 8) * 2;
    const uint32_t b_off = (uint32_t)((wn * 32 + (lane & 7)) * PITCH + ((lane >> 3) & 1) * 8) * 2;

    const int nch = K >> 5;
    load_stage(0, 0);

    for (int c = 0; c < nch; c++) {
        const int s = c & 1;
        if (c + 1 < nch) { load_stage(c + 1, s ^ 1); cp_wait<1>(); }
        else             { cp_wait<0>(); }
        __syncthreads();

        const uint32_t st = sbase + s * (STAGE_E * 2);
        const uint32_t Ahs = st;
        const uint32_t Bhs = st + A_MAT * 2;

#pragma unroll
        for (int kk = 0; kk < 32; kk += 16) {
            const uint32_t kb = kk * 2;
            uint32_t bf[4][2];
#pragma unroll
            for (int nt = 0; nt < 4; nt++)
                ldsm_x2(bf[nt], Bhs + b_off + (uint32_t)(nt * 8 * PITCH) * 2 + kb);
#pragma unroll
            for (int mt = 0; mt < 4; mt++) {
                uint32_t af[4];
                ldsm_x4(af, Ahs + a_off + (uint32_t)(mt * 16 * PITCH) * 2 + kb);
#pragma unroll
                for (int nt = 0; nt < 4; nt++)
                    mma_f16(acc[mt][nt], af, bf[nt]);
            }
        }
        __syncthreads();
    }

    // epilogue
#pragma unroll
    for (int mt = 0; mt < 4; mt++) {
#pragma unroll
        for (int nt = 0; nt < 4; nt++) {
            const int col = bx * 128 + wn * 32 + nt * 8 + tig * 2;
            const float2 bv = *(const float2*)&bias[col];
            const int row0 = by * 256 + wm * 64 + mt * 16 + gid;
#pragma unroll
            for (int half = 0; half < 2; half++) {
                const int row = row0 + half * 8;
                float v0 = acc[mt][nt][half * 2]     + bv.x;
                float v1 = acc[mt][nt][half * 2 + 1] + bv.y;
                if (RELU) { v0 = fmaxf(v0, 0.f); v1 = fmaxf(v1, 0.f); }
                const size_t o = (size_t)row * N + col;
                if (WF32) *(float2*)(C + o) = make_float2(v0, v1);
                if (WF16) {
                    __half2 hp;
                    hp.x = __float2half_rn(v0);
                    hp.y = __float2half_rn(v1);
                    *(__half2*)(Ch + o) = hp;
                }
            }
        }
    }
}

// ---------------- fp32 -> fp16 convert ----------------
__global__ __launch_bounds__(256)
void cvt_kernel(const float* __restrict__ src, __half* __restrict__ dst, int n4)
{
    int i = blockIdx.x * 256 + threadIdx.x;
    if (i >= n4) return;
    float4 v = ((const float4*)src)[i];
    __half2 a, b;
    a.x = __float2half_rn(v.x); a.y = __float2half_rn(v.y);
    b.x = __float2half_rn(v.z); b.y = __float2half_rn(v.w);
    ((__half2*)dst)[i*2]   = a;
    ((__half2*)dst)[i*2+1] = b;
}

// ---------------- banded flash attention (fp32 in, fp16 out) ----------------
__global__ __launch_bounds__(1024)
void attn_kernel(const float* __restrict__ qkv, __half* __restrict__ out_h)
{
    const int b  = blockIdx.z;
    const int h  = blockIdx.y;
    const int q0 = blockIdx.x * 32;
    const int warp = threadIdx.x >> 5;
    const int lane = threadIdx.x & 31;
    const int q = q0 + warp;

    const float* base = qkv + (size_t)b * SS * (3 * DD);
    const int hc = h * HD;

    const float q0r = base[(size_t)q * (3 * DD) + hc + lane];
    const float q1r = base[(size_t)q * (3 * DD) + hc + lane + 32];

    const int klo = max(q0 - WIN, 0);
    const int khi = min(q0 + 31 + WIN, SS - 1);

    __shared__ float Ks[32][64];
    __shared__ float Vs[32][64];

    float m = -1e30f, lsum = 0.f, acc0 = 0.f, acc1 = 0.f;

    for (int c = klo; c <= khi; c += 32) {
        const int nk = min(32, khi - c + 1);
        __syncthreads();
        for (int idx = threadIdx.x; idx < nk * 64; idx += 1024) {
            int j = idx >> 6, d = idx & 63;
            size_t row = (size_t)(c + j) * (3 * DD);
            Ks[j][d] = base[row + DD + hc + d];
            Vs[j][d] = base[row + 2 * DD + hc + d];
        }
        __syncthreads();

        const int jlo = max(q - WIN, c) - c;
        const int jhi = min(q + WIN, c + nk - 1) - c;
        for (int j = jlo; j <= jhi; j++) {
            float partial = q0r * Ks[j][lane] + q1r * Ks[j][lane + 32];
#pragma unroll
            for (int off = 16; off > 0; off >>= 1)
                partial += __shfl_xor_sync(0xFFFFFFFFu, partial, off);
            float s = partial * 0.125f;
            float nm = fmaxf(m, s);
            float scale = __expf(m - nm);
            float p = __expf(s - nm);
            lsum = lsum * scale + p;
            acc0 = acc0 * scale + p * Vs[j][lane];
            acc1 = acc1 * scale + p * Vs[j][lane + 32];
            m = nm;
        }
    }

    const float inv = 1.f / lsum;
    const size_t ob = ((size_t)b * SS + q) * DD + hc;
    out_h[ob + lane]      = __float2half_rn(acc0 * inv);
    out_h[ob + lane + 32] = __float2half_rn(acc1 * inv);
}

// ---------------- fused residual + LayerNorm (+ optional fp16 out) ----------------
__global__ __launch_bounds__(256)
void ln_kernel(const float* __restrict__ A, const float* __restrict__ R,
               const float* __restrict__ g, const float* __restrict__ be,
               float* __restrict__ out, __half* __restrict__ oh)
{
    const int row = blockIdx.x;
    const int t = threadIdx.x;
    const size_t base = (size_t)row * DD;

    float4 av = *(const float4*)(A + base + t * 4);
    float4 rv = *(const float4*)(R + base + t * 4);
    float4 v = make_float4(av.x + rv.x, av.y + rv.y, av.z + rv.z, av.w + rv.w);

    float s = v.x + v.y + v.z + v.w;
    float q = v.x * v.x + v.y * v.y + v.z * v.z + v.w * v.w;
#pragma unroll
    for (int off = 16; off > 0; off >>= 1) {
        s += __shfl_xor_sync(0xFFFFFFFFu, s, off);
        q += __shfl_xor_sync(0xFFFFFFFFu, q, off);
    }
    __shared__ float ss[8], sq[8];
    __shared__ float mu_s, inv_s;
    if ((t & 31) == 0) { ss[t >> 5] = s; sq[t >> 5] = q; }
    __syncthreads();
    if (t == 0) {
        float S = 0.f, Q = 0.f;
#pragma unroll
        for (int i = 0; i < 8; i++) { S += ss[i]; Q += sq[i]; }
        float mu = S * (1.f / DD);
        float var = Q * (1.f / DD) - mu * mu;
        mu_s = mu;
        inv_s = rsqrtf(var + 1e-5f);
    }
    __syncthreads();
    const float mu = mu_s, inv = inv_s;

    float4 gv = *(const float4*)(g + t * 4);
    float4 bv = *(const float4*)(be + t * 4);
    float4 o;
    o.x = (v.x - mu) * inv * gv.x + bv.x;
    o.y = (v.y - mu) * inv * gv.y + bv.y;
    o.z = (v.z - mu) * inv * gv.z + bv.z;
    o.w = (v.w - mu) * inv * gv.w + bv.w;
    *(float4*)(out + base + t * 4) = o;

    if (oh != nullptr) {
        __half2 h0, h1;
        h0.x = __float2half_rn(o.x); h0.y = __float2half_rn(o.y);
        h1.x = __float2half_rn(o.z); h1.y = __float2half_rn(o.w);
        *(__half2*)(oh + base + t * 4)     = h0;
        *(__half2*)(oh + base + t * 4 + 2) = h1;
    }
}

// ---------------- host ----------------
extern "C" void kernel_launch(void* const* d_in, const int* in_sizes, int n_in,
                              void* d_out, int out_size)
{
    (void)in_sizes; (void)n_in; (void)out_size;
    const float* x     = (const float*)d_in[0];
    const float* in_w  = (const float*)d_in[1];
    const float* in_b  = (const float*)d_in[2];
    const float* out_w = (const float*)d_in[3];
    const float* out_b = (const float*)d_in[4];
    const float* ln1g  = (const float*)d_in[5];
    const float* ln1b  = (const float*)d_in[6];
    const float* w1    = (const float*)d_in[7];
    const float* b1    = (const float*)d_in[8];
    const float* w2    = (const float*)d_in[9];
    const float* b2    = (const float*)d_in[10];
    const float* ln2g  = (const float*)d_in[11];
    const float* ln2b  = (const float*)d_in[12];
    float* out = (float*)d_out;

    float *qkv, *tmp, *x2;
    __half *xh, *ath, *x2h, *ffh, *iwh, *owh, *w1h, *w2h;
    cudaGetSymbolAddress((void**)&qkv, g_qkv);
    cudaGetSymbolAddress((void**)&tmp, g_tmp);
    cudaGetSymbolAddress((void**)&x2,  g_x2);
    cudaGetSymbolAddress((void**)&xh,  g_x_h);
    cudaGetSymbolAddress((void**)&ath, g_at_h);
    cudaGetSymbolAddress((void**)&x2h, g_x2_h);
    cudaGetSymbolAddress((void**)&ffh, g_ff_h);
    cudaGetSymbolAddress((void**)&iwh, g_iw_h);
    cudaGetSymbolAddress((void**)&owh, g_ow_h);
    cudaGetSymbolAddress((void**)&w1h, g_w1_h);
    cudaGetSymbolAddress((void**)&w2h, g_w2_h);

    cudaFuncSetAttribute(gemm_f16<false, true, false>,
                         cudaFuncAttributeMaxDynamicSharedMemorySize, GEMM_SMEM);
    cudaFuncSetAttribute(gemm_f16<true, false, true>,
                         cudaFuncAttributeMaxDynamicSharedMemorySize, GEMM_SMEM);

    // converts
    cvt_kernel<<<(MTOT * DD / 4 + 255) / 256, 256>>>(x,     xh,  MTOT * DD / 4);
    cvt_kernel<<<(3 * DD * DD / 4 + 255) / 256, 256>>>(in_w, iwh, 3 * DD * DD / 4);
    cvt_kernel<<<(DD * DD / 4 + 255) / 256, 256>>>(out_w,   owh, DD * DD / 4);
    cvt_kernel<<<(DFF * DD / 4 + 255) / 256, 256>>>(w1,     w1h, DFF * DD / 4);
    cvt_kernel<<<(DD * DFF / 4 + 255) / 256, 256>>>(w2,     w2h, DD * DFF / 4);

    // 1. QKV projection (fp32 out)
    gemm_f16<false, true, false><<<dim3(3 * DD / 128, MTOT / 256), 512, GEMM_SMEM>>>(
        xh, iwh, in_b, qkv, nullptr, MTOT, 3 * DD, DD);
    // 2. attention (fp16 out)
    attn_kernel<<<dim3(SS / 32, HH, BB), 1024>>>(qkv, ath);
    // 3. out_proj (fp32 out)
    gemm_f16<false, true, false><<<dim3(DD / 128, MTOT / 256), 512, GEMM_SMEM>>>(
        ath, owh, out_b, tmp, nullptr, MTOT, DD, DD);
    // 4. ln1 (fp32 + fp16 out)
    ln_kernel<<<MTOT, 256>>>(x, tmp, ln1g, ln1b, x2, x2h);
    // 5. ffn1 (relu, fp16 out only)
    gemm_f16<true, false, true><<<dim3(DFF / 128, MTOT / 256), 512, GEMM_SMEM>>>(
        x2h, w1h, b1, nullptr, ffh, MTOT, DFF, DD);
    // 6. ffn2 (fp32 out)
    gemm_f16<false, true, false><<<dim3(DD / 128, MTOT / 256), 512, GEMM_SMEM>>>(
        ffh, w2h, b2, tmp, nullptr, MTOT, DD, DFF);
    // 7. ln2 -> final out
    ln_kernel<<<MTOT, 256>>>(x2, tmp, ln2g, ln2b, out, nullptr);
}

// round 7
// speedup vs baseline: 6.8268x; 2.5706x over previous
#include <cuda_runtime.h>
#include <cuda_fp16.h>
#include <math.h>
#include <stdint.h>

#define BB   2
#define SS   2048
#define DD   1024
#define HH   16
#define HD   64
#define DFF  4096
#define WIN  128
#define MTOT (BB * SS)

// ---------------- device scratch ----------------
__device__ float  g_tmp [(size_t)MTOT * DD];
__device__ float  g_x2  [(size_t)MTOT * DD];
__device__ __half g_qkvh[(size_t)MTOT * 3 * DD];
__device__ __half g_x_h [(size_t)MTOT * DD];
__device__ __half g_at_h[(size_t)MTOT * DD];
__device__ __half g_x2_h[(size_t)MTOT * DD];
__device__ __half g_ff_h[(size_t)MTOT * DFF];
__device__ __half g_iw_h[(size_t)3*DD*DD];
__device__ __half g_ow_h[(size_t)DD*DD];
__device__ __half g_w1_h[(size_t)DFF*DD];
__device__ __half g_w2_h[(size_t)DD*DFF];

// ---------------- PTX helpers ----------------
__device__ __forceinline__ uint32_t smem_u32(const void* p) {
    uint32_t a;
    asm("{ .reg .u64 t; cvta.to.shared.u64 t, %1; cvt.u32.u64 %0, t; }" : "=r"(a) : "l"(p));
    return a;
}
__device__ __forceinline__ void cp16(uint32_t dst, const void* src) {
    asm volatile("cp.async.cg.shared.global [%0], [%1], 16;" :: "r"(dst), "l"(src));
}
__device__ __forceinline__ void cp_commit() {
    asm volatile("cp.async.commit_group;" ::: "memory");
}
template<int N>
__device__ __forceinline__ void cp_wait() {
    asm volatile("cp.async.wait_group %0;" :: "n"(N) : "memory");
}
__device__ __forceinline__ void mma_f16(float* c, const uint32_t* a, const uint32_t* b) {
    asm volatile(
        "mma.sync.aligned.m16n8k16.row.col.f32.f16.f16.f32 "
        "{%0,%1,%2,%3}, {%4,%5,%6,%7}, {%8,%9}, {%0,%1,%2,%3};"
        : "+f"(c[0]), "+f"(c[1]), "+f"(c[2]), "+f"(c[3])
        : "r"(a[0]), "r"(a[1]), "r"(a[2]), "r"(a[3]), "r"(b[0]), "r"(b[1]));
}
__device__ __forceinline__ void ldsm_x4(uint32_t* r, uint32_t addr) {
    asm volatile("ldmatrix.sync.aligned.m8n8.x4.shared.b16 {%0,%1,%2,%3}, [%4];"
                 : "=r"(r[0]), "=r"(r[1]), "=r"(r[2]), "=r"(r[3]) : "r"(addr));
}
__device__ __forceinline__ void ldsm_x2(uint32_t* r, uint32_t addr) {
    asm volatile("ldmatrix.sync.aligned.m8n8.x2.shared.b16 {%0,%1}, [%2];"
                 : "=r"(r[0]), "=r"(r[1]) : "r"(addr));
}
__device__ __forceinline__ void ldsm_x4_t(uint32_t* r, uint32_t addr) {
    asm volatile("ldmatrix.sync.aligned.m8n8.x4.trans.shared.b16 {%0,%1,%2,%3}, [%4];"
                 : "=r"(r[0]), "=r"(r[1]), "=r"(r[2]), "=r"(r[3]) : "r"(addr));
}

// ---------------- fp16 GEMM via mma.sync ----------------
// C[M,N] = A[M,K] @ B[N,K]^T + bias.  Block 256x128, BK=64, 512 thr,
// warp grid 4x4, warp tile 64x32.  Rows padded to 72 halves (144B).
#define PITCH   72
#define A_MAT   (256 * PITCH)              // 18432 elems
#define B_MAT   (128 * PITCH)              // 9216 elems
#define STAGE_E (A_MAT + B_MAT)            // 27648 elems
#define GEMM_SMEM (2 * STAGE_E * 2)        // 110592 bytes

template<bool RELU, bool WF32, bool WF16>
__global__ __launch_bounds__(512, 1)
void gemm_f16(const __half* __restrict__ A, const __half* __restrict__ B,
              const float* __restrict__ bias,
              float* __restrict__ C, __half* __restrict__ Ch,
              int M, int N, int K)
{
    extern __shared__ __align__(16) __half sm[];
    const uint32_t sbase = smem_u32(sm);
    const int tid  = threadIdx.x;
    const int warp = tid >> 5, lane = tid & 31;
    const int gid  = lane >> 2, tig = lane & 3;
    const int wm   = warp >> 2, wn = warp & 3;
    const int bx = blockIdx.x, by = blockIdx.y;

    const size_t Abase = (size_t)(by * 256) * K;
    const size_t Bbase = (size_t)(bx * 128) * K;

    // stage loader: A 2048 + B 1024 16B-units, 6 per thread
    auto load_stage = [&](int chunk, int s) {
        const int k0 = chunk * 64;
        const uint32_t sb = sbase + s * (STAGE_E * 2);
#pragma unroll
        for (int i = 0; i < 6; i++) {
            int idx = i * 512 + tid;
            if (idx < 2048) {
                int r = idx >> 3, c = idx & 7;
                cp16(sb + (uint32_t)(r * PITCH + c * 8) * 2,
                     A + Abase + (size_t)r * K + k0 + c * 8);
            } else {
                int j = idx - 2048;
                int r = j >> 3, c = j & 7;
                cp16(sb + (uint32_t)(A_MAT + r * PITCH + c * 8) * 2,
                     B + Bbase + (size_t)r * K + k0 + c * 8);
            }
        }
        cp_commit();
    };

    float acc[4][4][4];
#pragma unroll
    for (int i = 0; i < 4; i++)
#pragma unroll
        for (int j = 0; j < 4; j++)
#pragma unroll
            for (int v = 0; v < 4; v++) acc[i][j][v] = 0.f;

    const uint32_t a_off = (uint32_t)((wm * 64 + (lane & 15)) * PITCH) * 2 + (lane >> 4) * 16;
    const uint32_t b_off = (uint32_t)((wn * 32 + (lane & 7)) * PITCH) * 2 + ((lane >> 3) & 1) * 16;

    const int nch = K >> 6;
    load_stage(0, 0);

    for (int c = 0; c < nch; c++) {
        const int s = c & 1;
        if (c + 1 < nch) { load_stage(c + 1, s ^ 1); cp_wait<1>(); }
        else             { cp_wait<0>(); }
        __syncthreads();

        const uint32_t Ahs = sbase + s * (STAGE_E * 2);
        const uint32_t Bhs = Ahs + A_MAT * 2;

#pragma unroll
        for (int kk = 0; kk < 64; kk += 16) {
            uint32_t bf[4][2];
#pragma unroll
            for (int nt = 0; nt < 4; nt++)
                ldsm_x2(bf[nt], Bhs + b_off + (uint32_t)(nt * 8 * PITCH) * 2 + kk * 2);
#pragma unroll
            for (int mt = 0; mt < 4; mt++) {
                uint32_t af[4];
                ldsm_x4(af, Ahs + a_off + (uint32_t)(mt * 16 * PITCH) * 2 + kk * 2);
#pragma unroll
                for (int nt = 0; nt < 4; nt++)
                    mma_f16(acc[mt][nt], af, bf[nt]);
            }
        }
        __syncthreads();
    }

    // epilogue
#pragma unroll
    for (int mt = 0; mt < 4; mt++) {
#pragma unroll
        for (int nt = 0; nt < 4; nt++) {
            const int col = bx * 128 + wn * 32 + nt * 8 + tig * 2;
            const float2 bv = *(const float2*)&bias[col];
            const int row0 = by * 256 + wm * 64 + mt * 16 + gid;
#pragma unroll
            for (int half = 0; half < 2; half++) {
                const int row = row0 + half * 8;
                float v0 = acc[mt][nt][half * 2]     + bv.x;
                float v1 = acc[mt][nt][half * 2 + 1] + bv.y;
                if (RELU) { v0 = fmaxf(v0, 0.f); v1 = fmaxf(v1, 0.f); }
                const size_t o = (size_t)row * N + col;
                if (WF32) *(float2*)(C + o) = make_float2(v0, v1);
                if (WF16) {
                    __half2 hp;
                    hp.x = __float2half_rn(v0);
                    hp.y = __float2half_rn(v1);
                    *(__half2*)(Ch + o) = hp;
                }
            }
        }
    }
}

// ---------------- fp32 -> fp16 convert ----------------
__global__ __launch_bounds__(256)
void cvt_kernel(const float* __restrict__ src, __half* __restrict__ dst, int n4)
{
    int i = blockIdx.x * 256 + threadIdx.x;
    if (i >= n4) return;
    float4 v = ((const float4*)src)[i];
    __half2 a, b;
    a.x = __float2half_rn(v.x); a.y = __float2half_rn(v.y);
    b.x = __float2half_rn(v.z); b.y = __float2half_rn(v.w);
    ((__half2*)dst)[i*2]   = a;
    ((__half2*)dst)[i*2+1] = b;
}

// ---------------- MMA banded flash attention ----------------
// Block: 128 queries x 1 head x 1 batch; 8 warps, 16 q/warp.
// Smem (halves, pitch 72): Q 128x72 | K 32x72 | V 32x72  = 27648 B static.
__global__ __launch_bounds__(256)
void attn_mma(const __half* __restrict__ qkvh, __half* __restrict__ outh)
{
    __shared__ __align__(16) __half asmem[192 * 72];
    const uint32_t sQ = smem_u32(asmem);
    const uint32_t sK = sQ + 128 * 72 * 2;
    const uint32_t sV = sK + 32 * 72 * 2;
    __half* pK = asmem + 128 * 72;
    __half* pV = asmem + 160 * 72;

    const int tid = threadIdx.x, warp = tid >> 5, lane = tid & 31;
    const int gid = lane >> 2, tig = lane & 3;
    const int b = blockIdx.z, h = blockIdx.y, q0 = blockIdx.x * 128;
    const __half* base = qkvh + (size_t)b * SS * (3 * DD);

    // stage Q tile (128 x 64)
#pragma unroll
    for (int i = 0; i < 4; i++) {
        int idx = i * 256 + tid;
        int r = idx >> 3, c = idx & 7;
        cp16(sQ + (uint32_t)(r * PITCH + c * 8) * 2,
             base + (size_t)(q0 + r) * (3 * DD) + h * HD + c * 8);
    }
    cp_commit(); cp_wait<0>();
    __syncthreads();

    uint32_t qf[4][4];
    {
        const uint32_t qa = sQ + (uint32_t)((warp * 16 + (lane & 15)) * PITCH) * 2 + (lane >> 4) * 16;
#pragma unroll
        for (int kc = 0; kc < 4; kc++) ldsm_x4(qf[kc], qa + kc * 32);
    }

    float o[8][4];
#pragma unroll
    for (int i = 0; i < 8; i++)
#pragma unroll
        for (int j = 0; j < 4; j++) o[i][j] = 0.f;
    float m0 = -1e30f, m1 = -1e30f, l0 = 0.f, l1 = 0.f;

    const int row0 = q0 + warp * 16 + gid;
    const int row1 = row0 + 8;
    const int klo = max(q0 - WIN, 0);
    const int khi = min(q0 + 127 + WIN, SS - 1);

    for (int kt = klo; kt <= khi; kt += 32) {
        const int nk = khi - kt + 1 < 32 ? khi - kt + 1 : 32;
        __syncthreads();
        {   // stage K,V (zero-fill invalid rows)
            int r = tid >> 3, c = tid & 7;
            size_t grow = (size_t)(kt + r) * (3 * DD) + h * HD + c * 8;
            if (r < nk) cp16(sK + (uint32_t)(r * PITCH + c * 8) * 2, base + grow + DD);
            else        *(uint4*)(pK + r * PITCH + c * 8) = make_uint4(0, 0, 0, 0);
            if (r < nk) cp16(sV + (uint32_t)(r * PITCH + c * 8) * 2, base + grow + 2 * DD);
            else        *(uint4*)(pV + r * PITCH + c * 8) = make_uint4(0, 0, 0, 0);
            cp_commit(); cp_wait<0>();
        }
        __syncthreads();

        // S = Q K^T
        float sc[4][4];
#pragma unroll
        for (int nt = 0; nt < 4; nt++)
#pragma unroll
            for (int j = 0; j < 4; j++) sc[nt][j] = 0.f;
#pragma unroll
        for (int nt = 0; nt < 4; nt++) {
            const uint32_t kbase = sK + (uint32_t)((nt * 8 + (lane & 7)) * PITCH) * 2 + (lane >> 3) * 16;
#pragma unroll
            for (int kp = 0; kp < 2; kp++) {
                uint32_t kf[4];
                ldsm_x4(kf, kbase + kp * 64);
                mma_f16(sc[nt], qf[kp * 2],     &kf[0]);
                mma_f16(sc[nt], qf[kp * 2 + 1], &kf[2]);
            }
        }

        // scale + band mask
        float mx0 = -1e30f, mx1 = -1e30f;
#pragma unroll
        for (int nt = 0; nt < 4; nt++) {
            const int c0 = kt + nt * 8 + tig * 2, c1 = c0 + 1;
            float s;
            s = sc[nt][0] * 0.125f;
            sc[nt][0] = (c0 >= row0 - WIN && c0 <= row0 + WIN && c0 <= khi) ? s : -1e30f;
            s = sc[nt][1] * 0.125f;
            sc[nt][1] = (c1 >= row0 - WIN && c1 <= row0 + WIN && c1 <= khi) ? s : -1e30f;
            s = sc[nt][2] * 0.125f;
            sc[nt][2] = (c0 >= row1 - WIN && c0 <= row1 + WIN && c0 <= khi) ? s : -1e30f;
            s = sc[nt][3] * 0.125f;
            sc[nt][3] = (c1 >= row1 - WIN && c1 <= row1 + WIN && c1 <= khi) ? s : -1e30f;
            mx0 = fmaxf(mx0, fmaxf(sc[nt][0], sc[nt][1]));
            mx1 = fmaxf(mx1, fmaxf(sc[nt][2], sc[nt][3]));
        }
        mx0 = fmaxf(mx0, __shfl_xor_sync(0xFFFFFFFFu, mx0, 1));
        mx0 = fmaxf(mx0, __shfl_xor_sync(0xFFFFFFFFu, mx0, 2));
        mx1 = fmaxf(mx1, __shfl_xor_sync(0xFFFFFFFFu, mx1, 1));
        mx1 = fmaxf(mx1, __shfl_xor_sync(0xFFFFFFFFu, mx1, 2));

        const float nm0 = fmaxf(m0, mx0), nm1 = fmaxf(m1, mx1);
        const float e0 = __expf(m0 - nm0), e1 = __expf(m1 - nm1);
        l0 *= e0; l1 *= e1;
#pragma unroll
        for (int ng = 0; ng < 8; ng++) {
            o[ng][0] *= e0; o[ng][1] *= e0;
            o[ng][2] *= e1; o[ng][3] *= e1;
        }
        m0 = nm0; m1 = nm1;

        // P (fp16 A-fragments) + row sums
        uint32_t pf[2][4];
#pragma unroll
        for (int nt = 0; nt < 4; nt++) {
            float p0 = __expf(sc[nt][0] - nm0), p1 = __expf(sc[nt][1] - nm0);
            float p2 = __expf(sc[nt][2] - nm1), p3 = __expf(sc[nt][3] - nm1);
            l0 += p0 + p1; l1 += p2 + p3;
            __half2 h01 = __floats2half2_rn(p0, p1);
            __half2 h23 = __floats2half2_rn(p2, p3);
            pf[nt >> 1][(nt & 1) * 2 + 0] = *(uint32_t*)&h01;
            pf[nt >> 1][(nt & 1) * 2 + 1] = *(uint32_t*)&h23;
        }

        // O += P V  (V via ldmatrix.trans)
#pragma unroll
        for (int np = 0; np < 4; np++) {
#pragma unroll
            for (int kc = 0; kc < 2; kc++) {
                uint32_t vf[4];
                ldsm_x4_t(vf, sV + (uint32_t)((kc * 16 + (lane & 15)) * PITCH) * 2 +
                              (np * 2 + (lane >> 4)) * 16);
                mma_f16(o[np * 2],     pf[kc], &vf[0]);
                mma_f16(o[np * 2 + 1], pf[kc], &vf[2]);
            }
        }
    }

    // finalize
    l0 += __shfl_xor_sync(0xFFFFFFFFu, l0, 1);
    l0 += __shfl_xor_sync(0xFFFFFFFFu, l0, 2);
    l1 += __shfl_xor_sync(0xFFFFFFFFu, l1, 1);
    l1 += __shfl_xor_sync(0xFFFFFFFFu, l1, 2);
    const float inv0 = 1.f / l0, inv1 = 1.f / l1;
    __half* o0p = outh + (size_t)(b * SS + row0) * DD + h * HD + tig * 2;
    __half* o1p = outh + (size_t)(b * SS + row1) * DD + h * HD + tig * 2;
#pragma unroll
    for (int ng = 0; ng < 8; ng++) {
        __half2 a = __floats2half2_rn(o[ng][0] * inv0, o[ng][1] * inv0);
        __half2 c = __floats2half2_rn(o[ng][2] * inv1, o[ng][3] * inv1);
        *(__half2*)(o0p + ng * 8) = a;
        *(__half2*)(o1p + ng * 8) = c;
    }
}

// ---------------- fused residual + LayerNorm (+ optional fp16 out) ----------------
__global__ __launch_bounds__(256)
void ln_kernel(const float* __restrict__ A, const float* __restrict__ R,
               const float* __restrict__ g, const float* __restrict__ be,
               float* __restrict__ out, __half* __restrict__ oh)
{
    const int row = blockIdx.x;
    const int t = threadIdx.x;
    const size_t base = (size_t)row * DD;

    float4 av = *(const float4*)(A + base + t * 4);
    float4 rv = *(const float4*)(R + base + t * 4);
    float4 v = make_float4(av.x + rv.x, av.y + rv.y, av.z + rv.z, av.w + rv.w);

    float s = v.x + v.y + v.z + v.w;
    float q = v.x * v.x + v.y * v.y + v.z * v.z + v.w * v.w;
#pragma unroll
    for (int off = 16; off > 0; off >>= 1) {
        s += __shfl_xor_sync(0xFFFFFFFFu, s, off);
        q += __shfl_xor_sync(0xFFFFFFFFu, q, off);
    }
    __shared__ float ss[8], sq[8];
    __shared__ float mu_s, inv_s;
    if ((t & 31) == 0) { ss[t >> 5] = s; sq[t >> 5] = q; }
    __syncthreads();
    if (t == 0) {
        float S = 0.f, Q = 0.f;
#pragma unroll
        for (int i = 0; i < 8; i++) { S += ss[i]; Q += sq[i]; }
        float mu = S * (1.f / DD);
        float var = Q * (1.f / DD) - mu * mu;
        mu_s = mu;
        inv_s = rsqrtf(var + 1e-5f);
    }
    __syncthreads();
    const float mu = mu_s, inv = inv_s;

    float4 gv = *(const float4*)(g + t * 4);
    float4 bv = *(const float4*)(be + t * 4);
    float4 o;
    o.x = (v.x - mu) * inv * gv.x + bv.x;
    o.y = (v.y - mu) * inv * gv.y + bv.y;
    o.z = (v.z - mu) * inv * gv.z + bv.z;
    o.w = (v.w - mu) * inv * gv.w + bv.w;
    *(float4*)(out + base + t * 4) = o;

    if (oh != nullptr) {
        __half2 h0, h1;
        h0.x = __float2half_rn(o.x); h0.y = __float2half_rn(o.y);
        h1.x = __float2half_rn(o.z); h1.y = __float2half_rn(o.w);
        *(__half2*)(oh + base + t * 4)     = h0;
        *(__half2*)(oh + base + t * 4 + 2) = h1;
    }
}

// ---------------- host ----------------
extern "C" void kernel_launch(void* const* d_in, const int* in_sizes, int n_in,
                              void* d_out, int out_size)
{
    (void)in_sizes; (void)n_in; (void)out_size;
    const float* x     = (const float*)d_in[0];
    const float* in_w  = (const float*)d_in[1];
    const float* in_b  = (const float*)d_in[2];
    const float* out_w = (const float*)d_in[3];
    const float* out_b = (const float*)d_in[4];
    const float* ln1g  = (const float*)d_in[5];
    const float* ln1b  = (const float*)d_in[6];
    const float* w1    = (const float*)d_in[7];
    const float* b1    = (const float*)d_in[8];
    const float* w2    = (const float*)d_in[9];
    const float* b2    = (const float*)d_in[10];
    const float* ln2g  = (const float*)d_in[11];
    const float* ln2b  = (const float*)d_in[12];
    float* out = (float*)d_out;

    float *tmp, *x2;
    __half *qkvh, *xh, *ath, *x2h, *ffh, *iwh, *owh, *w1h, *w2h;
    cudaGetSymbolAddress((void**)&tmp,  g_tmp);
    cudaGetSymbolAddress((void**)&x2,   g_x2);
    cudaGetSymbolAddress((void**)&qkvh, g_qkvh);
    cudaGetSymbolAddress((void**)&xh,   g_x_h);
    cudaGetSymbolAddress((void**)&ath,  g_at_h);
    cudaGetSymbolAddress((void**)&x2h,  g_x2_h);
    cudaGetSymbolAddress((void**)&ffh,  g_ff_h);
    cudaGetSymbolAddress((void**)&iwh,  g_iw_h);
    cudaGetSymbolAddress((void**)&owh,  g_ow_h);
    cudaGetSymbolAddress((void**)&w1h,  g_w1_h);
    cudaGetSymbolAddress((void**)&w2h,  g_w2_h);

    cudaFuncSetAttribute(gemm_f16<false, true, false>,
                         cudaFuncAttributeMaxDynamicSharedMemorySize, GEMM_SMEM);
    cudaFuncSetAttribute(gemm_f16<false, false, true>,
                         cudaFuncAttributeMaxDynamicSharedMemorySize, GEMM_SMEM);
    cudaFuncSetAttribute(gemm_f16<true, false, true>,
                         cudaFuncAttributeMaxDynamicSharedMemorySize, GEMM_SMEM);

    // converts
    cvt_kernel<<<(MTOT * DD / 4 + 255) / 256, 256>>>(x,     xh,  MTOT * DD / 4);
    cvt_kernel<<<(3 * DD * DD / 4 + 255) / 256, 256>>>(in_w, iwh, 3 * DD * DD / 4);
    cvt_kernel<<<(DD * DD / 4 + 255) / 256, 256>>>(out_w,   owh, DD * DD / 4);
    cvt_kernel<<<(DFF * DD / 4 + 255) / 256, 256>>>(w1,     w1h, DFF * DD / 4);
    cvt_kernel<<<(DD * DFF / 4 + 255) / 256, 256>>>(w2,     w2h, DD * DFF / 4);

    // 1. QKV projection -> fp16 qkv
    gemm_f16<false, false, true><<<dim3(3 * DD / 128, MTOT / 256), 512, GEMM_SMEM>>>(
        xh, iwh, in_b, nullptr, qkvh, MTOT, 3 * DD, DD);
    // 2. MMA attention -> fp16
    attn_mma<<<dim3(SS / 128, HH, BB), 256>>>(qkvh, ath);
    // 3. out_proj -> fp32
    gemm_f16<false, true, false><<<dim3(DD / 128, MTOT / 256), 512, GEMM_SMEM>>>(
        ath, owh, out_b, tmp, nullptr, MTOT, DD, DD);
    // 4. ln1 -> fp32 + fp16
    ln_kernel<<<MTOT, 256>>>(x, tmp, ln1g, ln1b, x2, x2h);
    // 5. ffn1 (relu) -> fp16
    gemm_f16<true, false, true><<<dim3(DFF / 128, MTOT / 256), 512, GEMM_SMEM>>>(
        x2h, w1h, b1, nullptr, ffh, MTOT, DFF, DD);
    // 6. ffn2 -> fp32
    gemm_f16<false, true, false><<<dim3(DD / 128, MTOT / 256), 512, GEMM_SMEM>>>(
        ffh, w2h, b2, tmp, nullptr, MTOT, DD, DFF);
    // 7. ln2 -> final out
    ln_kernel<<<MTOT, 256>>>(x2, tmp, ln2g, ln2b, out, nullptr);
}

// round 8
// speedup vs baseline: 7.2715x; 1.0651x over previous
#include <cuda_runtime.h>
#include <cuda_fp16.h>
#include <math.h>
#include <stdint.h>

#define BB   2
#define SS   2048
#define DD   1024
#define HH   16
#define HD   64
#define DFF  4096
#define WIN  128
#define MTOT (BB * SS)

// ---------------- device scratch ----------------
__device__ float  g_tmp [(size_t)MTOT * DD];
__device__ float  g_x2  [(size_t)MTOT * DD];
__device__ __half g_qkvh[(size_t)MTOT * 3 * DD];
__device__ __half g_x_h [(size_t)MTOT * DD];
__device__ __half g_at_h[(size_t)MTOT * DD];
__device__ __half g_x2_h[(size_t)MTOT * DD];
__device__ __half g_ff_h[(size_t)MTOT * DFF];
__device__ __half g_iw_h[(size_t)3*DD*DD];
__device__ __half g_ow_h[(size_t)DD*DD];
__device__ __half g_w1_h[(size_t)DFF*DD];
__device__ __half g_w2_h[(size_t)DD*DFF];

// ---------------- PTX helpers ----------------
__device__ __forceinline__ uint32_t smem_u32(const void* p) {
    uint32_t a;
    asm("{ .reg .u64 t; cvta.to.shared.u64 t, %1; cvt.u32.u64 %0, t; }" : "=r"(a) : "l"(p));
    return a;
}
__device__ __forceinline__ void cp16(uint32_t dst, const void* src) {
    asm volatile("cp.async.cg.shared.global [%0], [%1], 16;" :: "r"(dst), "l"(src));
}
__device__ __forceinline__ void cp_commit() {
    asm volatile("cp.async.commit_group;" ::: "memory");
}
template<int N>
__device__ __forceinline__ void cp_wait() {
    asm volatile("cp.async.wait_group %0;" :: "n"(N) : "memory");
}
__device__ __forceinline__ void mma_f16(float* c, const uint32_t* a, const uint32_t* b) {
    asm volatile(
        "mma.sync.aligned.m16n8k16.row.col.f32.f16.f16.f32 "
        "{%0,%1,%2,%3}, {%4,%5,%6,%7}, {%8,%9}, {%0,%1,%2,%3};"
        : "+f"(c[0]), "+f"(c[1]), "+f"(c[2]), "+f"(c[3])
        : "r"(a[0]), "r"(a[1]), "r"(a[2]), "r"(a[3]), "r"(b[0]), "r"(b[1]));
}
__device__ __forceinline__ void ldsm_x4(uint32_t* r, uint32_t addr) {
    asm volatile("ldmatrix.sync.aligned.m8n8.x4.shared.b16 {%0,%1,%2,%3}, [%4];"
                 : "=r"(r[0]), "=r"(r[1]), "=r"(r[2]), "=r"(r[3]) : "r"(addr));
}
__device__ __forceinline__ void ldsm_x2(uint32_t* r, uint32_t addr) {
    asm volatile("ldmatrix.sync.aligned.m8n8.x2.shared.b16 {%0,%1}, [%2];"
                 : "=r"(r[0]), "=r"(r[1]) : "r"(addr));
}
__device__ __forceinline__ void ldsm_x4_t(uint32_t* r, uint32_t addr) {
    asm volatile("ldmatrix.sync.aligned.m8n8.x4.trans.shared.b16 {%0,%1,%2,%3}, [%4];"
                 : "=r"(r[0]), "=r"(r[1]), "=r"(r[2]), "=r"(r[3]) : "r"(addr));
}

// ---------------- fp16 GEMM via mma.sync ----------------
// C[M,N] = A[M,K] @ B[N,K]^T + bias.  Block 256x128, BK=64, 512 thr,
// warp grid 4x4, warp tile 64x32.  Rows padded to 72 halves. 3-stage pipeline.
#define PITCH   72
#define A_MAT   (256 * PITCH)
#define B_MAT   (128 * PITCH)
#define STAGE_E (A_MAT + B_MAT)            // 27648 elems
#define STAGE_B (STAGE_E * 2)              // 55296 bytes
#define GEMM_SMEM (3 * STAGE_B)            // 165888 bytes

template<bool RELU, bool WF32, bool WF16>
__global__ __launch_bounds__(512, 1)
void gemm_f16(const __half* __restrict__ A, const __half* __restrict__ B,
              const float* __restrict__ bias,
              float* __restrict__ C, __half* __restrict__ Ch,
              int M, int N, int K)
{
    extern __shared__ __align__(16) __half sm[];
    const uint32_t sbase = smem_u32(sm);
    const int tid  = threadIdx.x;
    const int warp = tid >> 5, lane = tid & 31;
    const int gid  = lane >> 2, tig = lane & 3;
    const int wm   = warp >> 2, wn = warp & 3;
    const int bx = blockIdx.x, by = blockIdx.y;

    const size_t Abase = (size_t)(by * 256) * K;
    const size_t Bbase = (size_t)(bx * 128) * K;

    auto load_stage = [&](int chunk, int s) {
        const int k0 = chunk * 64;
        const uint32_t sb = sbase + s * STAGE_B;
#pragma unroll
        for (int i = 0; i < 6; i++) {
            int idx = i * 512 + tid;
            if (idx < 2048) {
                int r = idx >> 3, c = idx & 7;
                cp16(sb + (uint32_t)(r * PITCH + c * 8) * 2,
                     A + Abase + (size_t)r * K + k0 + c * 8);
            } else {
                int j = idx - 2048;
                int r = j >> 3, c = j & 7;
                cp16(sb + (uint32_t)(A_MAT + r * PITCH + c * 8) * 2,
                     B + Bbase + (size_t)r * K + k0 + c * 8);
            }
        }
    };

    float acc[4][4][4];
#pragma unroll
    for (int i = 0; i < 4; i++)
#pragma unroll
        for (int j = 0; j < 4; j++)
#pragma unroll
            for (int v = 0; v < 4; v++) acc[i][j][v] = 0.f;

    const uint32_t a_off = (uint32_t)((wm * 64 + (lane & 15)) * PITCH) * 2 + (lane >> 4) * 16;
    const uint32_t b_off = (uint32_t)((wn * 32 + (lane & 7)) * PITCH) * 2 + ((lane >> 3) & 1) * 16;

    const int nch = K >> 6;
    load_stage(0, 0); cp_commit();
    load_stage(1, 1); cp_commit();

    for (int c = 0; c < nch; c++) {
        cp_wait<1>();
        __syncthreads();
        if (c + 2 < nch) load_stage(c + 2, (c + 2) % 3);
        cp_commit();                      // constant 1 group per iter

        const uint32_t Ahs = sbase + (c % 3) * STAGE_B;
        const uint32_t Bhs = Ahs + A_MAT * 2;

#pragma unroll
        for (int kk = 0; kk < 64; kk += 16) {
            uint32_t bf[4][2];
#pragma unroll
            for (int nt = 0; nt < 4; nt++)
                ldsm_x2(bf[nt], Bhs + b_off + (uint32_t)(nt * 8 * PITCH) * 2 + kk * 2);
#pragma unroll
            for (int mt = 0; mt < 4; mt++) {
                uint32_t af[4];
                ldsm_x4(af, Ahs + a_off + (uint32_t)(mt * 16 * PITCH) * 2 + kk * 2);
#pragma unroll
                for (int nt = 0; nt < 4; nt++)
                    mma_f16(acc[mt][nt], af, bf[nt]);
            }
        }
    }

    // epilogue
#pragma unroll
    for (int mt = 0; mt < 4; mt++) {
#pragma unroll
        for (int nt = 0; nt < 4; nt++) {
            const int col = bx * 128 + wn * 32 + nt * 8 + tig * 2;
            const float2 bv = *(const float2*)&bias[col];
            const int row0 = by * 256 + wm * 64 + mt * 16 + gid;
#pragma unroll
            for (int half = 0; half < 2; half++) {
                const int row = row0 + half * 8;
                float v0 = acc[mt][nt][half * 2]     + bv.x;
                float v1 = acc[mt][nt][half * 2 + 1] + bv.y;
                if (RELU) { v0 = fmaxf(v0, 0.f); v1 = fmaxf(v1, 0.f); }
                const size_t o = (size_t)row * N + col;
                if (WF32) *(float2*)(C + o) = make_float2(v0, v1);
                if (WF16) {
                    __half2 hp;
                    hp.x = __float2half_rn(v0);
                    hp.y = __float2half_rn(v1);
                    *(__half2*)(Ch + o) = hp;
                }
            }
        }
    }
}

// ---------------- fused fp32->fp16 conversions (all 5 tensors, one launch) ----
#define N4_X   1048576
#define N4_IW  786432
#define N4_OW  262144
#define N4_W1  1048576
#define N4_W2  1048576
#define N4_TOT 4194304

__global__ __launch_bounds__(256)
void cvt_all(const float* __restrict__ x,  __half* __restrict__ xh,
             const float* __restrict__ iw, __half* __restrict__ iwh,
             const float* __restrict__ ow, __half* __restrict__ owh,
             const float* __restrict__ w1, __half* __restrict__ w1h,
             const float* __restrict__ w2, __half* __restrict__ w2h)
{
    int i = blockIdx.x * 256 + threadIdx.x;
    if (i >= N4_TOT) return;
    const float* s; __half* d; int off;
    if      (i < N4_X)                         { s = x;  d = xh;  off = 0; }
    else if (i < N4_X + N4_IW)                 { s = iw; d = iwh; off = N4_X; }
    else if (i < N4_X + N4_IW + N4_OW)         { s = ow; d = owh; off = N4_X + N4_IW; }
    else if (i < N4_X + N4_IW + N4_OW + N4_W1) { s = w1; d = w1h; off = N4_X + N4_IW + N4_OW; }
    else                                       { s = w2; d = w2h; off = N4_X + N4_IW + N4_OW + N4_W1; }
    int j = i - off;
    float4 v = ((const float4*)s)[j];
    __half2 a, b;
    a.x = __float2half_rn(v.x); a.y = __float2half_rn(v.y);
    b.x = __float2half_rn(v.z); b.y = __float2half_rn(v.w);
    ((__half2*)d)[j*2]   = a;
    ((__half2*)d)[j*2+1] = b;
}

// ---------------- MMA banded flash attention, 3-stage K/V pipeline ----------
// Block: 128 queries x 1 head x 1 batch; 8 warps, 16 q/warp.
// Smem: Q 128x72 | 3 stages of (K 32x72 + V 32x72) = 46080 B static.
__global__ __launch_bounds__(256)
void attn_mma(const __half* __restrict__ qkvh, __half* __restrict__ outh)
{
    __shared__ __align__(16) __half asmem[(128 + 3 * 64) * 72];
    const uint32_t sQ = smem_u32(asmem);

    const int tid = threadIdx.x, warp = tid >> 5, lane = tid & 31;
    const int gid = lane >> 2, tig = lane & 3;
    const int b = blockIdx.z, h = blockIdx.y, q0 = blockIdx.x * 128;
    const __half* base = qkvh + (size_t)b * SS * (3 * DD);

    const int row0 = q0 + warp * 16 + gid;
    const int row1 = row0 + 8;
    const int klo = max(q0 - WIN, 0);
    const int khi = min(q0 + 127 + WIN, SS - 1);
    const int ntiles = (khi - klo + 32) / 32;

    auto load_kv = [&](int it, int s) {
        const int kt = klo + it * 32;
        const int nk = khi - kt + 1 < 32 ? khi - kt + 1 : 32;
        const uint32_t sK = sQ + (uint32_t)(128 + s * 64) * 72 * 2;
        const uint32_t sV = sK + 32 * 72 * 2;
        __half* pK = asmem + (128 + s * 64) * 72;
        __half* pV = pK + 32 * 72;
        int r = tid >> 3, c = tid & 7;
        size_t grow = (size_t)(kt + r) * (3 * DD) + h * HD + c * 8;
        if (r < nk) cp16(sK + (uint32_t)(r * PITCH + c * 8) * 2, base + grow + DD);
        else        *(uint4*)(pK + r * PITCH + c * 8) = make_uint4(0, 0, 0, 0);
        if (r < nk) cp16(sV + (uint32_t)(r * PITCH + c * 8) * 2, base + grow + 2 * DD);
        else        *(uint4*)(pV + r * PITCH + c * 8) = make_uint4(0, 0, 0, 0);
    };

    // prologue: Q + KV(0) in group 0, KV(1) in group 1
#pragma unroll
    for (int i = 0; i < 4; i++) {
        int idx = i * 256 + tid;
        int r = idx >> 3, c = idx & 7;
        cp16(sQ + (uint32_t)(r * PITCH + c * 8) * 2,
             base + (size_t)(q0 + r) * (3 * DD) + h * HD + c * 8);
    }
    load_kv(0, 0); cp_commit();
    if (ntiles > 1) load_kv(1, 1);
    cp_commit();

    uint32_t qf[4][4];
    float o[8][4];
#pragma unroll
    for (int i = 0; i < 8; i++)
#pragma unroll
        for (int j = 0; j < 4; j++) o[i][j] = 0.f;
    float m0 = -1e30f, m1 = -1e30f, l0 = 0.f, l1 = 0.f;

    for (int it = 0; it < ntiles; it++) {
        cp_wait<1>();
        __syncthreads();
        if (it + 2 < ntiles) load_kv(it + 2, (it + 2) % 3);
        cp_commit();

        if (it == 0) {
            const uint32_t qa = sQ + (uint32_t)((warp * 16 + (lane & 15)) * PITCH) * 2 + (lane >> 4) * 16;
#pragma unroll
            for (int kc = 0; kc < 4; kc++) ldsm_x4(qf[kc], qa + kc * 32);
        }

        const int kt = klo + it * 32;
        const int s = it % 3;
        const uint32_t sK = sQ + (uint32_t)(128 + s * 64) * 72 * 2;
        const uint32_t sV = sK + 32 * 72 * 2;

        // S = Q K^T
        float sc[4][4];
#pragma unroll
        for (int nt = 0; nt < 4; nt++)
#pragma unroll
            for (int j = 0; j < 4; j++) sc[nt][j] = 0.f;
#pragma unroll
        for (int nt = 0; nt < 4; nt++) {
            const uint32_t kbase = sK + (uint32_t)((nt * 8 + (lane & 7)) * PITCH) * 2 + (lane >> 3) * 16;
#pragma unroll
            for (int kp = 0; kp < 2; kp++) {
                uint32_t kf[4];
                ldsm_x4(kf, kbase + kp * 64);
                mma_f16(sc[nt], qf[kp * 2],     &kf[0]);
                mma_f16(sc[nt], qf[kp * 2 + 1], &kf[2]);
            }
        }

        // scale + band mask
        float mx0 = -1e30f, mx1 = -1e30f;
#pragma unroll
        for (int nt = 0; nt < 4; nt++) {
            const int c0 = kt + nt * 8 + tig * 2, c1 = c0 + 1;
            float s2;
            s2 = sc[nt][0] * 0.125f;
            sc[nt][0] = (c0 >= row0 - WIN && c0 <= row0 + WIN && c0 <= khi) ? s2 : -1e30f;
            s2 = sc[nt][1] * 0.125f;
            sc[nt][1] = (c1 >= row0 - WIN && c1 <= row0 + WIN && c1 <= khi) ? s2 : -1e30f;
            s2 = sc[nt][2] * 0.125f;
            sc[nt][2] = (c0 >= row1 - WIN && c0 <= row1 + WIN && c0 <= khi) ? s2 : -1e30f;
            s2 = sc[nt][3] * 0.125f;
            sc[nt][3] = (c1 >= row1 - WIN && c1 <= row1 + WIN && c1 <= khi) ? s2 : -1e30f;
            mx0 = fmaxf(mx0, fmaxf(sc[nt][0], sc[nt][1]));
            mx1 = fmaxf(mx1, fmaxf(sc[nt][2], sc[nt][3]));
        }
        mx0 = fmaxf(mx0, __shfl_xor_sync(0xFFFFFFFFu, mx0, 1));
        mx0 = fmaxf(mx0, __shfl_xor_sync(0xFFFFFFFFu, mx0, 2));
        mx1 = fmaxf(mx1, __shfl_xor_sync(0xFFFFFFFFu, mx1, 1));
        mx1 = fmaxf(mx1, __shfl_xor_sync(0xFFFFFFFFu, mx1, 2));

        const float nm0 = fmaxf(m0, mx0), nm1 = fmaxf(m1, mx1);
        const float e0 = __expf(m0 - nm0), e1 = __expf(m1 - nm1);
        l0 *= e0; l1 *= e1;
#pragma unroll
        for (int ng = 0; ng < 8; ng++) {
            o[ng][0] *= e0; o[ng][1] *= e0;
            o[ng][2] *= e1; o[ng][3] *= e1;
        }
        m0 = nm0; m1 = nm1;

        // P (fp16 A-fragments) + row sums
        uint32_t pf[2][4];
#pragma unroll
        for (int nt = 0; nt < 4; nt++) {
            float p0 = __expf(sc[nt][0] - nm0), p1 = __expf(sc[nt][1] - nm0);
            float p2 = __expf(sc[nt][2] - nm1), p3 = __expf(sc[nt][3] - nm1);
            l0 += p0 + p1; l1 += p2 + p3;
            __half2 h01 = __floats2half2_rn(p0, p1);
            __half2 h23 = __floats2half2_rn(p2, p3);
            pf[nt >> 1][(nt & 1) * 2 + 0] = *(uint32_t*)&h01;
            pf[nt >> 1][(nt & 1) * 2 + 1] = *(uint32_t*)&h23;
        }

        // O += P V
#pragma unroll
        for (int np = 0; np < 4; np++) {
#pragma unroll
            for (int kc = 0; kc < 2; kc++) {
                uint32_t vf[4];
                ldsm_x4_t(vf, sV + (uint32_t)((kc * 16 + (lane & 15)) * PITCH) * 2 +
                              (np * 2 + (lane >> 4)) * 16);
                mma_f16(o[np * 2],     pf[kc], &vf[0]);
                mma_f16(o[np * 2 + 1], pf[kc], &vf[2]);
            }
        }
    }

    // finalize
    l0 += __shfl_xor_sync(0xFFFFFFFFu, l0, 1);
    l0 += __shfl_xor_sync(0xFFFFFFFFu, l0, 2);
    l1 += __shfl_xor_sync(0xFFFFFFFFu, l1, 1);
    l1 += __shfl_xor_sync(0xFFFFFFFFu, l1, 2);
    const float inv0 = 1.f / l0, inv1 = 1.f / l1;
    __half* o0p = outh + (size_t)(b * SS + row0) * DD + h * HD + tig * 2;
    __half* o1p = outh + (size_t)(b * SS + row1) * DD + h * HD + tig * 2;
#pragma unroll
    for (int ng = 0; ng < 8; ng++) {
        __half2 a = __floats2half2_rn(o[ng][0] * inv0, o[ng][1] * inv0);
        __half2 c = __floats2half2_rn(o[ng][2] * inv1, o[ng][3] * inv1);
        *(__half2*)(o0p + ng * 8) = a;
        *(__half2*)(o1p + ng * 8) = c;
    }
}

// ---------------- fused residual + LayerNorm (+ optional fp16 out) ----------------
__global__ __launch_bounds__(256)
void ln_kernel(const float* __restrict__ A, const float* __restrict__ R,
               const float* __restrict__ g, const float* __restrict__ be,
               float* __restrict__ out, __half* __restrict__ oh)
{
    const int row = blockIdx.x;
    const int t = threadIdx.x;
    const size_t base = (size_t)row * DD;

    float4 av = *(const float4*)(A + base + t * 4);
    float4 rv = *(const float4*)(R + base + t * 4);
    float4 v = make_float4(av.x + rv.x, av.y + rv.y, av.z + rv.z, av.w + rv.w);

    float s = v.x + v.y + v.z + v.w;
    float q = v.x * v.x + v.y * v.y + v.z * v.z + v.w * v.w;
#pragma unroll
    for (int off = 16; off > 0; off >>= 1) {
        s += __shfl_xor_sync(0xFFFFFFFFu, s, off);
        q += __shfl_xor_sync(0xFFFFFFFFu, q, off);
    }
    __shared__ float ss[8], sq[8];
    __shared__ float mu_s, inv_s;
    if ((t & 31) == 0) { ss[t >> 5] = s; sq[t >> 5] = q; }
    __syncthreads();
    if (t == 0) {
        float S = 0.f, Q = 0.f;
#pragma unroll
        for (int i = 0; i < 8; i++) { S += ss[i]; Q += sq[i]; }
        float mu = S * (1.f / DD);
        float var = Q * (1.f / DD) - mu * mu;
        mu_s = mu;
        inv_s = rsqrtf(var + 1e-5f);
    }
    __syncthreads();
    const float mu = mu_s, inv = inv_s;

    float4 gv = *(const float4*)(g + t * 4);
    float4 bv = *(const float4*)(be + t * 4);
    float4 o;
    o.x = (v.x - mu) * inv * gv.x + bv.x;
    o.y = (v.y - mu) * inv * gv.y + bv.y;
    o.z = (v.z - mu) * inv * gv.z + bv.z;
    o.w = (v.w - mu) * inv * gv.w + bv.w;
    *(float4*)(out + base + t * 4) = o;

    if (oh != nullptr) {
        __half2 h0, h1;
        h0.x = __float2half_rn(o.x); h0.y = __float2half_rn(o.y);
        h1.x = __float2half_rn(o.z); h1.y = __float2half_rn(o.w);
        *(__half2*)(oh + base + t * 4)     = h0;
        *(__half2*)(oh + base + t * 4 + 2) = h1;
    }
}

// ---------------- host ----------------
extern "C" void kernel_launch(void* const* d_in, const int* in_sizes, int n_in,
                              void* d_out, int out_size)
{
    (void)in_sizes; (void)n_in; (void)out_size;
    const float* x     = (const float*)d_in[0];
    const float* in_w  = (const float*)d_in[1];
    const float* in_b  = (const float*)d_in[2];
    const float* out_w = (const float*)d_in[3];
    const float* out_b = (const float*)d_in[4];
    const float* ln1g  = (const float*)d_in[5];
    const float* ln1b  = (const float*)d_in[6];
    const float* w1    = (const float*)d_in[7];
    const float* b1    = (const float*)d_in[8];
    const float* w2    = (const float*)d_in[9];
    const float* b2    = (const float*)d_in[10];
    const float* ln2g  = (const float*)d_in[11];
    const float* ln2b  = (const float*)d_in[12];
    float* out = (float*)d_out;

    float *tmp, *x2;
    __half *qkvh, *xh, *ath, *x2h, *ffh, *iwh, *owh, *w1h, *w2h;
    cudaGetSymbolAddress((void**)&tmp,  g_tmp);
    cudaGetSymbolAddress((void**)&x2,   g_x2);
    cudaGetSymbolAddress((void**)&qkvh, g_qkvh);
    cudaGetSymbolAddress((void**)&xh,   g_x_h);
    cudaGetSymbolAddress((void**)&ath,  g_at_h);
    cudaGetSymbolAddress((void**)&x2h,  g_x2_h);
    cudaGetSymbolAddress((void**)&ffh,  g_ff_h);
    cudaGetSymbolAddress((void**)&iwh,  g_iw_h);
    cudaGetSymbolAddress((void**)&owh,  g_ow_h);
    cudaGetSymbolAddress((void**)&w1h,  g_w1_h);
    cudaGetSymbolAddress((void**)&w2h,  g_w2_h);

    cudaFuncSetAttribute(gemm_f16<false, true, false>,
                         cudaFuncAttributeMaxDynamicSharedMemorySize, GEMM_SMEM);
    cudaFuncSetAttribute(gemm_f16<false, false, true>,
                         cudaFuncAttributeMaxDynamicSharedMemorySize, GEMM_SMEM);
    cudaFuncSetAttribute(gemm_f16<true, false, true>,
                         cudaFuncAttributeMaxDynamicSharedMemorySize, GEMM_SMEM);

    // all converts in one launch
    cvt_all<<<(N4_TOT + 255) / 256, 256>>>(x, xh, in_w, iwh, out_w, owh, w1, w1h, w2, w2h);

    // 1. QKV projection -> fp16 qkv
    gemm_f16<false, false, true><<<dim3(3 * DD / 128, MTOT / 256), 512, GEMM_SMEM>>>(
        xh, iwh, in_b, nullptr, qkvh, MTOT, 3 * DD, DD);
    // 2. MMA attention -> fp16
    attn_mma<<<dim3(SS / 128, HH, BB), 256>>>(qkvh, ath);
    // 3. out_proj -> fp32
    gemm_f16<false, true, false><<<dim3(DD / 128, MTOT / 256), 512, GEMM_SMEM>>>(
        ath, owh, out_b, tmp, nullptr, MTOT, DD, DD);
    // 4. ln1 -> fp32 + fp16
    ln_kernel<<<MTOT, 256>>>(x, tmp, ln1g, ln1b, x2, x2h);
    // 5. ffn1 (relu) -> fp16
    gemm_f16<true, false, true><<<dim3(DFF / 128, MTOT / 256), 512, GEMM_SMEM>>>(
        x2h, w1h, b1, nullptr, ffh, MTOT, DFF, DD);
    // 6. ffn2 -> fp32
    gemm_f16<false, true, false><<<dim3(DD / 128, MTOT / 256), 512, GEMM_SMEM>>>(
        ffh, w2h, b2, tmp, nullptr, MTOT, DD, DFF);
    // 7. ln2 -> final out
    ln_kernel<<<MTOT, 256>>>(x2, tmp, ln2g, ln2b, out, nullptr);
}

// round 9
// speedup vs baseline: 7.7615x; 1.0674x over previous
#include <cuda_runtime.h>
#include <cuda_fp16.h>
#include <math.h>
#include <stdint.h>

#define BB   2
#define SS   2048
#define DD   1024
#define HH   16
#define HD   64
#define DFF  4096
#define WIN  128
#define MTOT (BB * SS)

// ---------------- device scratch ----------------
__device__ float  g_tmp [(size_t)MTOT * DD];
__device__ float  g_x2  [(size_t)MTOT * DD];
__device__ __half g_qkvh[(size_t)MTOT * 3 * DD];
__device__ __half g_x_h [(size_t)MTOT * DD];
__device__ __half g_at_h[(size_t)MTOT * DD];
__device__ __half g_x2_h[(size_t)MTOT * DD];
__device__ __half g_ff_h[(size_t)MTOT * DFF];
__device__ __half g_iw_h[(size_t)3*DD*DD];
__device__ __half g_ow_h[(size_t)DD*DD];
__device__ __half g_w1_h[(size_t)DFF*DD];
__device__ __half g_w2_h[(size_t)DD*DFF];

// ---------------- PTX helpers ----------------
__device__ __forceinline__ uint32_t smem_u32(const void* p) {
    uint32_t a;
    asm("{ .reg .u64 t; cvta.to.shared.u64 t, %1; cvt.u32.u64 %0, t; }" : "=r"(a) : "l"(p));
    return a;
}
__device__ __forceinline__ void cp16(uint32_t dst, const void* src) {
    asm volatile("cp.async.cg.shared.global [%0], [%1], 16;" :: "r"(dst), "l"(src));
}
__device__ __forceinline__ void cp_commit() {
    asm volatile("cp.async.commit_group;" ::: "memory");
}
template<int N>
__device__ __forceinline__ void cp_wait() {
    asm volatile("cp.async.wait_group %0;" :: "n"(N) : "memory");
}
__device__ __forceinline__ void mma_f16(float* c, const uint32_t* a, const uint32_t* b) {
    asm volatile(
        "mma.sync.aligned.m16n8k16.row.col.f32.f16.f16.f32 "
        "{%0,%1,%2,%3}, {%4,%5,%6,%7}, {%8,%9}, {%0,%1,%2,%3};"
        : "+f"(c[0]), "+f"(c[1]), "+f"(c[2]), "+f"(c[3])
        : "r"(a[0]), "r"(a[1]), "r"(a[2]), "r"(a[3]), "r"(b[0]), "r"(b[1]));
}
__device__ __forceinline__ void ldsm_x4(uint32_t* r, uint32_t addr) {
    asm volatile("ldmatrix.sync.aligned.m8n8.x4.shared.b16 {%0,%1,%2,%3}, [%4];"
                 : "=r"(r[0]), "=r"(r[1]), "=r"(r[2]), "=r"(r[3]) : "r"(addr));
}
__device__ __forceinline__ void ldsm_x2(uint32_t* r, uint32_t addr) {
    asm volatile("ldmatrix.sync.aligned.m8n8.x2.shared.b16 {%0,%1}, [%2];"
                 : "=r"(r[0]), "=r"(r[1]) : "r"(addr));
}
__device__ __forceinline__ void ldsm_x4_t(uint32_t* r, uint32_t addr) {
    asm volatile("ldmatrix.sync.aligned.m8n8.x4.trans.shared.b16 {%0,%1,%2,%3}, [%4];"
                 : "=r"(r[0]), "=r"(r[1]), "=r"(r[2]), "=r"(r[3]) : "r"(addr));
}

// ---------------- fp16 GEMM via mma.sync ----------------
// C[M,N] = A[M,K] @ B[N,K]^T + bias.  Block 128x128, BK=64, 256 thr,
// warp grid 2(m)x4(n), warp tile 64x32.  Rows padded to 72 halves.
// 3-stage pipeline, 110.6KB smem -> 2 CTAs/SM, 128 regs -> RF exactly full.
#define PITCH   72
#define A_MAT   (128 * PITCH)
#define B_MAT   (128 * PITCH)
#define STAGE_E (A_MAT + B_MAT)            // 18432 elems
#define STAGE_B (STAGE_E * 2)              // 36864 bytes
#define GEMM_SMEM (3 * STAGE_B)            // 110592 bytes

template<bool RELU, bool WF32, bool WF16>
__global__ __launch_bounds__(256, 2)
void gemm_f16(const __half* __restrict__ A, const __half* __restrict__ B,
              const float* __restrict__ bias,
              float* __restrict__ C, __half* __restrict__ Ch,
              int M, int N, int K)
{
    extern __shared__ __align__(16) __half sm[];
    const uint32_t sbase = smem_u32(sm);
    const int tid  = threadIdx.x;
    const int warp = tid >> 5, lane = tid & 31;
    const int gid  = lane >> 2, tig = lane & 3;
    const int wm   = warp >> 2, wn = warp & 3;     // 2 x 4
    const int bx = blockIdx.x, by = blockIdx.y;

    const size_t Abase = (size_t)(by * 128) * K;
    const size_t Bbase = (size_t)(bx * 128) * K;

    // stage loader: A 1024 + B 1024 16B-units, 8 per thread
    auto load_stage = [&](int chunk, int s) {
        const int k0 = chunk * 64;
        const uint32_t sb = sbase + s * STAGE_B;
#pragma unroll
        for (int i = 0; i < 8; i++) {
            int idx = i * 256 + tid;
            if (idx < 1024) {
                int r = idx >> 3, c = idx & 7;
                cp16(sb + (uint32_t)(r * PITCH + c * 8) * 2,
                     A + Abase + (size_t)r * K + k0 + c * 8);
            } else {
                int j = idx - 1024;
                int r = j >> 3, c = j & 7;
                cp16(sb + (uint32_t)(A_MAT + r * PITCH + c * 8) * 2,
                     B + Bbase + (size_t)r * K + k0 + c * 8);
            }
        }
    };

    float acc[4][4][4];
#pragma unroll
    for (int i = 0; i < 4; i++)
#pragma unroll
        for (int j = 0; j < 4; j++)
#pragma unroll
            for (int v = 0; v < 4; v++) acc[i][j][v] = 0.f;

    const uint32_t a_off = (uint32_t)((wm * 64 + (lane & 15)) * PITCH) * 2 + (lane >> 4) * 16;
    const uint32_t b_off = (uint32_t)((wn * 32 + (lane & 7)) * PITCH) * 2 + ((lane >> 3) & 1) * 16;

    const int nch = K >> 6;
    load_stage(0, 0); cp_commit();
    load_stage(1, 1); cp_commit();

    for (int c = 0; c < nch; c++) {
        cp_wait<1>();
        __syncthreads();
        if (c + 2 < nch) load_stage(c + 2, (c + 2) % 3);
        cp_commit();                      // constant 1 group per iter

        const uint32_t Ahs = sbase + (c % 3) * STAGE_B;
        const uint32_t Bhs = Ahs + A_MAT * 2;

#pragma unroll
        for (int kk = 0; kk < 64; kk += 16) {
            uint32_t bf[4][2];
#pragma unroll
            for (int nt = 0; nt < 4; nt++)
                ldsm_x2(bf[nt], Bhs + b_off + (uint32_t)(nt * 8 * PITCH) * 2 + kk * 2);
#pragma unroll
            for (int mt = 0; mt < 4; mt++) {
                uint32_t af[4];
                ldsm_x4(af, Ahs + a_off + (uint32_t)(mt * 16 * PITCH) * 2 + kk * 2);
#pragma unroll
                for (int nt = 0; nt < 4; nt++)
                    mma_f16(acc[mt][nt], af, bf[nt]);
            }
        }
    }

    // epilogue
#pragma unroll
    for (int mt = 0; mt < 4; mt++) {
#pragma unroll
        for (int nt = 0; nt < 4; nt++) {
            const int col = bx * 128 + wn * 32 + nt * 8 + tig * 2;
            const float2 bv = *(const float2*)&bias[col];
            const int row0 = by * 128 + wm * 64 + mt * 16 + gid;
#pragma unroll
            for (int half = 0; half < 2; half++) {
                const int row = row0 + half * 8;
                float v0 = acc[mt][nt][half * 2]     + bv.x;
                float v1 = acc[mt][nt][half * 2 + 1] + bv.y;
                if (RELU) { v0 = fmaxf(v0, 0.f); v1 = fmaxf(v1, 0.f); }
                const size_t o = (size_t)row * N + col;
                if (WF32) *(float2*)(C + o) = make_float2(v0, v1);
                if (WF16) {
                    __half2 hp;
                    hp.x = __float2half_rn(v0);
                    hp.y = __float2half_rn(v1);
                    *(__half2*)(Ch + o) = hp;
                }
            }
        }
    }
}

// ---------------- fused fp32->fp16 conversions (all 5 tensors, one launch) ----
#define N4_X   1048576
#define N4_IW  786432
#define N4_OW  262144
#define N4_W1  1048576
#define N4_W2  1048576
#define N4_TOT 4194304

__global__ __launch_bounds__(256)
void cvt_all(const float* __restrict__ x,  __half* __restrict__ xh,
             const float* __restrict__ iw, __half* __restrict__ iwh,
             const float* __restrict__ ow, __half* __restrict__ owh,
             const float* __restrict__ w1, __half* __restrict__ w1h,
             const float* __restrict__ w2, __half* __restrict__ w2h)
{
    int i = blockIdx.x * 256 + threadIdx.x;
    if (i >= N4_TOT) return;
    const float* s; __half* d; int off;
    if      (i < N4_X)                         { s = x;  d = xh;  off = 0; }
    else if (i < N4_X + N4_IW)                 { s = iw; d = iwh; off = N4_X; }
    else if (i < N4_X + N4_IW + N4_OW)         { s = ow; d = owh; off = N4_X + N4_IW; }
    else if (i < N4_X + N4_IW + N4_OW + N4_W1) { s = w1; d = w1h; off = N4_X + N4_IW + N4_OW; }
    else                                       { s = w2; d = w2h; off = N4_X + N4_IW + N4_OW + N4_W1; }
    int j = i - off;
    float4 v = ((const float4*)s)[j];
    __half2 a, b;
    a.x = __float2half_rn(v.x); a.y = __float2half_rn(v.y);
    b.x = __float2half_rn(v.z); b.y = __float2half_rn(v.w);
    ((__half2*)d)[j*2]   = a;
    ((__half2*)d)[j*2+1] = b;
}

// ---------------- MMA banded flash attention, 3-stage K/V pipeline ----------
__global__ __launch_bounds__(256)
void attn_mma(const __half* __restrict__ qkvh, __half* __restrict__ outh)
{
    __shared__ __align__(16) __half asmem[(128 + 3 * 64) * 72];
    const uint32_t sQ = smem_u32(asmem);

    const int tid = threadIdx.x, warp = tid >> 5, lane = tid & 31;
    const int gid = lane >> 2, tig = lane & 3;
    const int b = blockIdx.z, h = blockIdx.y, q0 = blockIdx.x * 128;
    const __half* base = qkvh + (size_t)b * SS * (3 * DD);

    const int row0 = q0 + warp * 16 + gid;
    const int row1 = row0 + 8;
    const int klo = max(q0 - WIN, 0);
    const int khi = min(q0 + 127 + WIN, SS - 1);
    const int ntiles = (khi - klo + 32) / 32;

    auto load_kv = [&](int it, int s) {
        const int kt = klo + it * 32;
        const int nk = khi - kt + 1 < 32 ? khi - kt + 1 : 32;
        const uint32_t sK = sQ + (uint32_t)(128 + s * 64) * 72 * 2;
        const uint32_t sV = sK + 32 * 72 * 2;
        __half* pK = asmem + (128 + s * 64) * 72;
        __half* pV = pK + 32 * 72;
        int r = tid >> 3, c = tid & 7;
        size_t grow = (size_t)(kt + r) * (3 * DD) + h * HD + c * 8;
        if (r < nk) cp16(sK + (uint32_t)(r * PITCH + c * 8) * 2, base + grow + DD);
        else        *(uint4*)(pK + r * PITCH + c * 8) = make_uint4(0, 0, 0, 0);
        if (r < nk) cp16(sV + (uint32_t)(r * PITCH + c * 8) * 2, base + grow + 2 * DD);
        else        *(uint4*)(pV + r * PITCH + c * 8) = make_uint4(0, 0, 0, 0);
    };

#pragma unroll
    for (int i = 0; i < 4; i++) {
        int idx = i * 256 + tid;
        int r = idx >> 3, c = idx & 7;
        cp16(sQ + (uint32_t)(r * PITCH + c * 8) * 2,
             base + (size_t)(q0 + r) * (3 * DD) + h * HD + c * 8);
    }
    load_kv(0, 0); cp_commit();
    if (ntiles > 1) load_kv(1, 1);
    cp_commit();

    uint32_t qf[4][4];
    float o[8][4];
#pragma unroll
    for (int i = 0; i < 8; i++)
#pragma unroll
        for (int j = 0; j < 4; j++) o[i][j] = 0.f;
    float m0 = -1e30f, m1 = -1e30f, l0 = 0.f, l1 = 0.f;

    for (int it = 0; it < ntiles; it++) {
        cp_wait<1>();
        __syncthreads();
        if (it + 2 < ntiles) load_kv(it + 2, (it + 2) % 3);
        cp_commit();

        if (it == 0) {
            const uint32_t qa = sQ + (uint32_t)((warp * 16 + (lane & 15)) * PITCH) * 2 + (lane >> 4) * 16;
#pragma unroll
            for (int kc = 0; kc < 4; kc++) ldsm_x4(qf[kc], qa + kc * 32);
        }

        const int kt = klo + it * 32;
        const int s = it % 3;
        const uint32_t sK = sQ + (uint32_t)(128 + s * 64) * 72 * 2;
        const uint32_t sV = sK + 32 * 72 * 2;

        float sc[4][4];
#pragma unroll
        for (int nt = 0; nt < 4; nt++)
#pragma unroll
            for (int j = 0; j < 4; j++) sc[nt][j] = 0.f;
#pragma unroll
        for (int nt = 0; nt < 4; nt++) {
            const uint32_t kbase = sK + (uint32_t)((nt * 8 + (lane & 7)) * PITCH) * 2 + (lane >> 3) * 16;
#pragma unroll
            for (int kp = 0; kp < 2; kp++) {
                uint32_t kf[4];
                ldsm_x4(kf, kbase + kp * 64);
                mma_f16(sc[nt], qf[kp * 2],     &kf[0]);
                mma_f16(sc[nt], qf[kp * 2 + 1], &kf[2]);
            }
        }

        float mx0 = -1e30f, mx1 = -1e30f;
#pragma unroll
        for (int nt = 0; nt < 4; nt++) {
            const int c0 = kt + nt * 8 + tig * 2, c1 = c0 + 1;
            float s2;
            s2 = sc[nt][0] * 0.125f;
            sc[nt][0] = (c0 >= row0 - WIN && c0 <= row0 + WIN && c0 <= khi) ? s2 : -1e30f;
            s2 = sc[nt][1] * 0.125f;
            sc[nt][1] = (c1 >= row0 - WIN && c1 <= row0 + WIN && c1 <= khi) ? s2 : -1e30f;
            s2 = sc[nt][2] * 0.125f;
            sc[nt][2] = (c0 >= row1 - WIN && c0 <= row1 + WIN && c0 <= khi) ? s2 : -1e30f;
            s2 = sc[nt][3] * 0.125f;
            sc[nt][3] = (c1 >= row1 - WIN && c1 <= row1 + WIN && c1 <= khi) ? s2 : -1e30f;
            mx0 = fmaxf(mx0, fmaxf(sc[nt][0], sc[nt][1]));
            mx1 = fmaxf(mx1, fmaxf(sc[nt][2], sc[nt][3]));
        }
        mx0 = fmaxf(mx0, __shfl_xor_sync(0xFFFFFFFFu, mx0, 1));
        mx0 = fmaxf(mx0, __shfl_xor_sync(0xFFFFFFFFu, mx0, 2));
        mx1 = fmaxf(mx1, __shfl_xor_sync(0xFFFFFFFFu, mx1, 1));
        mx1 = fmaxf(mx1, __shfl_xor_sync(0xFFFFFFFFu, mx1, 2));

        const float nm0 = fmaxf(m0, mx0), nm1 = fmaxf(m1, mx1);
        const float e0 = __expf(m0 - nm0), e1 = __expf(m1 - nm1);
        l0 *= e0; l1 *= e1;
#pragma unroll
        for (int ng = 0; ng < 8; ng++) {
            o[ng][0] *= e0; o[ng][1] *= e0;
            o[ng][2] *= e1; o[ng][3] *= e1;
        }
        m0 = nm0; m1 = nm1;

        uint32_t pf[2][4];
#pragma unroll
        for (int nt = 0; nt < 4; nt++) {
            float p0 = __expf(sc[nt][0] - nm0), p1 = __expf(sc[nt][1] - nm0);
            float p2 = __expf(sc[nt][2] - nm1), p3 = __expf(sc[nt][3] - nm1);
            l0 += p0 + p1; l1 += p2 + p3;
            __half2 h01 = __floats2half2_rn(p0, p1);
            __half2 h23 = __floats2half2_rn(p2, p3);
            pf[nt >> 1][(nt & 1) * 2 + 0] = *(uint32_t*)&h01;
            pf[nt >> 1][(nt & 1) * 2 + 1] = *(uint32_t*)&h23;
        }

#pragma unroll
        for (int np = 0; np < 4; np++) {
#pragma unroll
            for (int kc = 0; kc < 2; kc++) {
                uint32_t vf[4];
                ldsm_x4_t(vf, sV + (uint32_t)((kc * 16 + (lane & 15)) * PITCH) * 2 +
                              (np * 2 + (lane >> 4)) * 16);
                mma_f16(o[np * 2],     pf[kc], &vf[0]);
                mma_f16(o[np * 2 + 1], pf[kc], &vf[2]);
            }
        }
    }

    l0 += __shfl_xor_sync(0xFFFFFFFFu, l0, 1);
    l0 += __shfl_xor_sync(0xFFFFFFFFu, l0, 2);
    l1 += __shfl_xor_sync(0xFFFFFFFFu, l1, 1);
    l1 += __shfl_xor_sync(0xFFFFFFFFu, l1, 2);
    const float inv0 = 1.f / l0, inv1 = 1.f / l1;
    __half* o0p = outh + (size_t)(b * SS + row0) * DD + h * HD + tig * 2;
    __half* o1p = outh + (size_t)(b * SS + row1) * DD + h * HD + tig * 2;
#pragma unroll
    for (int ng = 0; ng < 8; ng++) {
        __half2 a = __floats2half2_rn(o[ng][0] * inv0, o[ng][1] * inv0);
        __half2 c = __floats2half2_rn(o[ng][2] * inv1, o[ng][3] * inv1);
        *(__half2*)(o0p + ng * 8) = a;
        *(__half2*)(o1p + ng * 8) = c;
    }
}

// ---------------- fused residual + LayerNorm (+ optional fp16 out) ----------------
__global__ __launch_bounds__(256)
void ln_kernel(const float* __restrict__ A, const float* __restrict__ R,
               const float* __restrict__ g, const float* __restrict__ be,
               float* __restrict__ out, __half* __restrict__ oh)
{
    const int row = blockIdx.x;
    const int t = threadIdx.x;
    const size_t base = (size_t)row * DD;

    float4 av = *(const float4*)(A + base + t * 4);
    float4 rv = *(const float4*)(R + base + t * 4);
    float4 v = make_float4(av.x + rv.x, av.y + rv.y, av.z + rv.z, av.w + rv.w);

    float s = v.x + v.y + v.z + v.w;
    float q = v.x * v.x + v.y * v.y + v.z * v.z + v.w * v.w;
#pragma unroll
    for (int off = 16; off > 0; off >>= 1) {
        s += __shfl_xor_sync(0xFFFFFFFFu, s, off);
        q += __shfl_xor_sync(0xFFFFFFFFu, q, off);
    }
    __shared__ float ss[8], sq[8];
    __shared__ float mu_s, inv_s;
    if ((t & 31) == 0) { ss[t >> 5] = s; sq[t >> 5] = q; }
    __syncthreads();
    if (t == 0) {
        float S = 0.f, Q = 0.f;
#pragma unroll
        for (int i = 0; i < 8; i++) { S += ss[i]; Q += sq[i]; }
        float mu = S * (1.f / DD);
        float var = Q * (1.f / DD) - mu * mu;
        mu_s = mu;
        inv_s = rsqrtf(var + 1e-5f);
    }
    __syncthreads();
    const float mu = mu_s, inv = inv_s;

    float4 gv = *(const float4*)(g + t * 4);
    float4 bv = *(const float4*)(be + t * 4);
    float4 o;
    o.x = (v.x - mu) * inv * gv.x + bv.x;
    o.y = (v.y - mu) * inv * gv.y + bv.y;
    o.z = (v.z - mu) * inv * gv.z + bv.z;
    o.w = (v.w - mu) * inv * gv.w + bv.w;
    *(float4*)(out + base + t * 4) = o;

    if (oh != nullptr) {
        __half2 h0, h1;
        h0.x = __float2half_rn(o.x); h0.y = __float2half_rn(o.y);
        h1.x = __float2half_rn(o.z); h1.y = __float2half_rn(o.w);
        *(__half2*)(oh + base + t * 4)     = h0;
        *(__half2*)(oh + base + t * 4 + 2) = h1;
    }
}

// ---------------- host ----------------
extern "C" void kernel_launch(void* const* d_in, const int* in_sizes, int n_in,
                              void* d_out, int out_size)
{
    (void)in_sizes; (void)n_in; (void)out_size;
    const float* x     = (const float*)d_in[0];
    const float* in_w  = (const float*)d_in[1];
    const float* in_b  = (const float*)d_in[2];
    const float* out_w = (const float*)d_in[3];
    const float* out_b = (const float*)d_in[4];
    const float* ln1g  = (const float*)d_in[5];
    const float* ln1b  = (const float*)d_in[6];
    const float* w1    = (const float*)d_in[7];
    const float* b1    = (const float*)d_in[8];
    const float* w2    = (const float*)d_in[9];
    const float* b2    = (const float*)d_in[10];
    const float* ln2g  = (const float*)d_in[11];
    const float* ln2b  = (const float*)d_in[12];
    float* out = (float*)d_out;

    float *tmp, *x2;
    __half *qkvh, *xh, *ath, *x2h, *ffh, *iwh, *owh, *w1h, *w2h;
    cudaGetSymbolAddress((void**)&tmp,  g_tmp);
    cudaGetSymbolAddress((void**)&x2,   g_x2);
    cudaGetSymbolAddress((void**)&qkvh, g_qkvh);
    cudaGetSymbolAddress((void**)&xh,   g_x_h);
    cudaGetSymbolAddress((void**)&ath,  g_at_h);
    cudaGetSymbolAddress((void**)&x2h,  g_x2_h);
    cudaGetSymbolAddress((void**)&ffh,  g_ff_h);
    cudaGetSymbolAddress((void**)&iwh,  g_iw_h);
    cudaGetSymbolAddress((void**)&owh,  g_ow_h);
    cudaGetSymbolAddress((void**)&w1h,  g_w1_h);
    cudaGetSymbolAddress((void**)&w2h,  g_w2_h);

    cudaFuncSetAttribute(gemm_f16<false, true, false>,
                         cudaFuncAttributeMaxDynamicSharedMemorySize, GEMM_SMEM);
    cudaFuncSetAttribute(gemm_f16<false, false, true>,
                         cudaFuncAttributeMaxDynamicSharedMemorySize, GEMM_SMEM);
    cudaFuncSetAttribute(gemm_f16<true, false, true>,
                         cudaFuncAttributeMaxDynamicSharedMemorySize, GEMM_SMEM);

    cvt_all<<<(N4_TOT + 255) / 256, 256>>>(x, xh, in_w, iwh, out_w, owh, w1, w1h, w2, w2h);

    // 1. QKV projection -> fp16 qkv
    gemm_f16<false, false, true><<<dim3(3 * DD / 128, MTOT / 128), 256, GEMM_SMEM>>>(
        xh, iwh, in_b, nullptr, qkvh, MTOT, 3 * DD, DD);
    // 2. MMA attention -> fp16
    attn_mma<<<dim3(SS / 128, HH, BB), 256>>>(qkvh, ath);
    // 3. out_proj -> fp32
    gemm_f16<false, true, false><<<dim3(DD / 128, MTOT / 128), 256, GEMM_SMEM>>>(
        ath, owh, out_b, tmp, nullptr, MTOT, DD, DD);
    // 4. ln1 -> fp32 + fp16
    ln_kernel<<<MTOT, 256>>>(x, tmp, ln1g, ln1b, x2, x2h);
    // 5. ffn1 (relu) -> fp16
    gemm_f16<true, false, true><<<dim3(DFF / 128, MTOT / 128), 256, GEMM_SMEM>>>(
        x2h, w1h, b1, nullptr, ffh, MTOT, DFF, DD);
    // 6. ffn2 -> fp32
    gemm_f16<false, true, false><<<dim3(DD / 128, MTOT / 128), 256, GEMM_SMEM>>>(
        ffh, w2h, b2, tmp, nullptr, MTOT, DD, DFF);
    // 7. ln2 -> final out
    ln_kernel<<<MTOT, 256>>>(x2, tmp, ln2g, ln2b, out, nullptr);
}